// round 12
// baseline (speedup 1.0000x reference)
#include <cuda_runtime.h>
#include <cuda_fp16.h>
#include <math.h>
#include <stdint.h>

// Problem constants
#define BATCH   4
#define TSEQ    2048
#define NHEAD   16
#define HSIZE   64
#define CEMB    1024
#define MROWS   (BATCH*TSEQ)   // 8192

// Scratch (device globals; fp16 operands, fp32 accum everywhere)
__device__ __half g_xh [(size_t)MROWS * CEMB];
__device__ __half g_qh [(size_t)BATCH * NHEAD * TSEQ * HSIZE]; // [B,H,T,D], q pre-scaled
__device__ __half g_kh [(size_t)BATCH * NHEAD * TSEQ * HSIZE]; // [B,H,T,D]
__device__ __half g_vh [(size_t)BATCH * NHEAD * TSEQ * HSIZE]; // [B,H,D,T] (transposed)
__device__ __half g_ah [(size_t)MROWS * CEMB];
__device__ __half g_wtq[(size_t)3 * CEMB * CEMB];              // [3C][C] K-major
__device__ __half g_wtp[(size_t)CEMB * CEMB];                  // [C][C]  K-major

// ---------------------------------------------------------------------------
// helpers
// ---------------------------------------------------------------------------
__device__ __forceinline__ void mma_f16(float& c0, float& c1, float& c2, float& c3,
                                        uint32_t a0, uint32_t a1, uint32_t a2, uint32_t a3,
                                        uint32_t b0, uint32_t b1) {
    asm volatile("mma.sync.aligned.m16n8k16.row.col.f32.f16.f16.f32 "
                 "{%0,%1,%2,%3}, {%4,%5,%6,%7}, {%8,%9}, {%0,%1,%2,%3};"
                 : "+f"(c0), "+f"(c1), "+f"(c2), "+f"(c3)
                 : "r"(a0), "r"(a1), "r"(a2), "r"(a3), "r"(b0), "r"(b1));
}
__device__ __forceinline__ uint32_t h2u(__half2 h) { return *(uint32_t*)&h; }
__device__ __forceinline__ uint32_t smem_u32(const void* p) {
    uint32_t a;
    asm("{ .reg .u64 t; cvta.to.shared.u64 t, %1; cvt.u32.u64 %0, t; }" : "=r"(a) : "l"(p));
    return a;
}
#define CP_ASYNC16(dst, src) \
    asm volatile("cp.async.cg.shared.global [%0], [%1], 16;" :: "r"(dst), "l"(src))
#define CP_COMMIT()  asm volatile("cp.async.commit_group;" ::)
#define CP_WAIT(n)   asm volatile("cp.async.wait_group %0;" :: "n"(n))

// ---------------------------------------------------------------------------
// x -> half
// ---------------------------------------------------------------------------
__global__ __launch_bounds__(256) void cvt_x(const float* __restrict__ in,
                                             __half* __restrict__ out)
{
    size_t i = ((size_t)blockIdx.x * 256 + threadIdx.x) * 8;
    float4 v0 = *(const float4*)(in + i);
    float4 v1 = *(const float4*)(in + i + 4);
    uint4 u = {h2u(__floats2half2_rn(v0.x, v0.y)), h2u(__floats2half2_rn(v0.z, v0.w)),
               h2u(__floats2half2_rn(v1.x, v1.y)), h2u(__floats2half2_rn(v1.z, v1.w))};
    *(uint4*)(out + i) = u;
}

// ---------------------------------------------------------------------------
// Weight transpose fp32 [R][C] -> half [C][R]
// ---------------------------------------------------------------------------
__global__ __launch_bounds__(256) void transpose_h(const float* __restrict__ in,
                                                   __half* __restrict__ out, int R, int C)
{
    __shared__ float t[32][33];
    int bx = blockIdx.x * 32, by = blockIdx.y * 32;
#pragma unroll
    for (int i = 0; i < 32; i += 8)
        t[threadIdx.y + i][threadIdx.x] = in[(size_t)(by + threadIdx.y + i) * C + bx + threadIdx.x];
    __syncthreads();
#pragma unroll
    for (int i = 0; i < 32; i += 8)
        out[(size_t)(bx + threadIdx.y + i) * R + by + threadIdx.x] =
            __float2half_rn(t[threadIdx.x][threadIdx.y + i]);
}

// ---------------------------------------------------------------------------
// fp16 GEMM (round-11 version, measured good): 128x128 tile, cp.async 3-stage,
// 2 CTAs/SM.
// ---------------------------------------------------------------------------
#define GA_H   (128 * 64)
#define GB_H   (128 * 64)
#define GST_H  (GA_H + GB_H)      // 32KB per stage
#define GSTAGES 3
__global__ __launch_bounds__(256, 2) void gemm_h(
    const __half* __restrict__ A, const __half* __restrict__ Bt,
    const float* __restrict__ bias, float* __restrict__ C,
    int M, int N, int K, int mode)
{
    extern __shared__ __align__(16) __half hsm[];
    const uint32_t sb = smem_u32(hsm);

    const int tid  = threadIdx.x;
    const int wid  = tid >> 5;
    const int lane = tid & 31;
    const int g    = lane >> 2;
    const int t    = lane & 3;
    const int wm   = wid & 3;
    const int wn   = wid >> 2;
    const int m0 = blockIdx.y * 128;
    const int n0 = blockIdx.x * 128;

    const int lrA = tid >> 3;
    const int lsA = tid & 7;

    float c[2][8][4];
#pragma unroll
    for (int mt = 0; mt < 2; ++mt)
#pragma unroll
        for (int nt = 0; nt < 8; ++nt)
#pragma unroll
            for (int j = 0; j < 4; ++j) c[mt][nt][j] = 0.f;

    auto issue = [&](int s) {
        const int base = (s % GSTAGES) * GST_H;
        const int koff = (s << 6) + lsA * 8;
#pragma unroll
        for (int i = 0; i < 4; ++i) {
            int r = lrA + i * 32;
            uint32_t dst = sb + (uint32_t)(base + r * 64 + ((lsA ^ (r & 7)) * 8)) * 2;
            CP_ASYNC16(dst, A + (size_t)(m0 + r) * K + koff);
        }
#pragma unroll
        for (int i = 0; i < 4; ++i) {
            int r = lrA + i * 32;
            uint32_t dst = sb + (uint32_t)(base + GA_H + r * 64 + ((lsA ^ (r & 7)) * 8)) * 2;
            CP_ASYNC16(dst, Bt + (size_t)(n0 + r) * K + koff);
        }
        CP_COMMIT();
    };

    const int KS = K >> 6;
    issue(0);
    issue(1);

#pragma unroll 1
    for (int s = 0; s < KS; ++s) {
        if (s + 1 < KS) { CP_WAIT(1); } else { CP_WAIT(0); }
        __syncthreads();
        if (s + 2 < KS) issue(s + 2);

        const __half* As = hsm + (s % GSTAGES) * GST_H;
        const __half* Bs = As + GA_H;

#pragma unroll
        for (int kt = 0; kt < 4; ++kt) {
            uint32_t bf[8][2];
#pragma unroll
            for (int nt = 0; nt < 8; ++nt) {
                int n = wn * 64 + nt * 8 + g;
                bf[nt][0] = *(const uint32_t*)&Bs[n * 64 + (((2 * kt) ^ g) * 8) + 2 * t];
                bf[nt][1] = *(const uint32_t*)&Bs[n * 64 + (((2 * kt + 1) ^ g) * 8) + 2 * t];
            }
#pragma unroll
            for (int mt = 0; mt < 2; ++mt) {
                int mb = wm * 32 + mt * 16;
                uint32_t a0 = *(const uint32_t*)&As[(mb + g) * 64 + (((2 * kt) ^ g) * 8) + 2 * t];
                uint32_t a1 = *(const uint32_t*)&As[(mb + g + 8) * 64 + (((2 * kt) ^ g) * 8) + 2 * t];
                uint32_t a2 = *(const uint32_t*)&As[(mb + g) * 64 + (((2 * kt + 1) ^ g) * 8) + 2 * t];
                uint32_t a3 = *(const uint32_t*)&As[(mb + g + 8) * 64 + (((2 * kt + 1) ^ g) * 8) + 2 * t];
#pragma unroll
                for (int nt = 0; nt < 8; ++nt)
                    mma_f16(c[mt][nt][0], c[mt][nt][1], c[mt][nt][2], c[mt][nt][3],
                            a0, a1, a2, a3, bf[nt][0], bf[nt][1]);
            }
        }
    }

    const int nbase = n0 + wn * 64;
    if (mode == 0) {
        const int which = nbase >> 10;
        const int h = (nbase & 1023) >> 6;
#pragma unroll
        for (int mt = 0; mt < 2; ++mt) {
            int r0 = m0 + wm * 32 + mt * 16 + g;
            int bb0 = r0 >> 11, tt0 = r0 & (TSEQ - 1);
            int r1 = r0 + 8;
            int bb1 = r1 >> 11, tt1 = r1 & (TSEQ - 1);
            if (which == 2) {
                __half* base0 = g_vh + ((size_t)(bb0 * NHEAD + h)) * HSIZE * TSEQ;
                __half* base1 = g_vh + ((size_t)(bb1 * NHEAD + h)) * HSIZE * TSEQ;
#pragma unroll
                for (int nt = 0; nt < 8; ++nt) {
                    int d = nt * 8 + 2 * t;
                    base0[(size_t)d * TSEQ + tt0]       = __float2half_rn(c[mt][nt][0]);
                    base0[(size_t)(d + 1) * TSEQ + tt0] = __float2half_rn(c[mt][nt][1]);
                    base1[(size_t)d * TSEQ + tt1]       = __float2half_rn(c[mt][nt][2]);
                    base1[(size_t)(d + 1) * TSEQ + tt1] = __float2half_rn(c[mt][nt][3]);
                }
            } else {
                const float sc = (which == 0) ? 0.125f : 1.0f;
                __half* base = (which == 0) ? g_qh : g_kh;
                __half* d0 = base + (((size_t)(bb0 * NHEAD + h) * TSEQ) + tt0) * HSIZE;
                __half* d1 = base + (((size_t)(bb1 * NHEAD + h) * TSEQ) + tt1) * HSIZE;
#pragma unroll
                for (int nt = 0; nt < 8; ++nt) {
                    int d = nt * 8 + 2 * t;
                    *(__half2*)(d0 + d) = __floats2half2_rn(c[mt][nt][0] * sc, c[mt][nt][1] * sc);
                    *(__half2*)(d1 + d) = __floats2half2_rn(c[mt][nt][2] * sc, c[mt][nt][3] * sc);
                }
            }
        }
    } else {
#pragma unroll
        for (int mt = 0; mt < 2; ++mt) {
            int r0 = m0 + wm * 32 + mt * 16 + g;
#pragma unroll
            for (int nt = 0; nt < 8; ++nt) {
                int n = nbase + nt * 8 + 2 * t;
                float2 bv = *(const float2*)(bias + n);
                float2 v0 = {c[mt][nt][0] + bv.x, c[mt][nt][1] + bv.y};
                float2 v1 = {c[mt][nt][2] + bv.x, c[mt][nt][3] + bv.y};
                *(float2*)(C + (size_t)r0 * N + n) = v0;
                *(float2*)(C + (size_t)(r0 + 8) * N + n) = v1;
            }
        }
    }
}

// ---------------------------------------------------------------------------
// fp16 causal flash attention, 2 CTAs/SM.
// 128-key KV tiles (cp.async double-buffered) processed as TWO 64-key halves:
// per half, s[8][4] (32 regs) -> online softmax -> P -> PV mma. Keeps regs
// under 128 so two CTAs co-reside and fill each other's softmax bubbles.
// Smem: QP [128][128]h (32KB) + 2 x KV (32KB) = 96KB/CTA.
// ---------------------------------------------------------------------------
#define AQP_H (128 * 128)
#define AK_H  (128 * 64)
#define KV_H  (AK_H + 64 * 128)   // 16384 halfs per buffer
__global__ __launch_bounds__(256, 2) void attn_h()
{
    extern __shared__ __align__(16) __half asm_[];
    __half* Qs = asm_;
    __half* Ps = Qs;
    const uint32_t sb = smem_u32(asm_);

    const int tid  = threadIdx.x;
    const int wid  = tid >> 5;
    const int lane = tid & 31;
    const int g    = lane >> 2;
    const int t    = lane & 3;
    const int mb   = wid * 16;
    const int bh   = blockIdx.y;
    const int qb   = gridDim.x - 1 - blockIdx.x;   // heavy CTAs first
    const int q0   = qb * 128;

    const __half* Kg = g_kh + (size_t)bh * TSEQ * HSIZE;
    const __half* Vg = g_vh + (size_t)bh * HSIZE * TSEQ;

    auto issueKV = [&](int jt) {
        const int base = AQP_H + (jt & 1) * KV_H;
#pragma unroll
        for (int i = 0; i < 4; ++i) {
            int f = tid + i * 256;
            int kr = f >> 3, ks = f & 7;
            uint32_t dst = sb + (uint32_t)(base + kr * 64 + ((ks ^ (kr & 7)) * 8)) * 2;
            CP_ASYNC16(dst, Kg + (size_t)(jt * 128 + kr) * HSIZE + ks * 8);
        }
#pragma unroll
        for (int i = 0; i < 4; ++i) {
            int f = tid + i * 256;
            int vr = f >> 4, vs = f & 15;
            uint32_t dst = sb + (uint32_t)(base + AK_H + vr * 128 + ((vs ^ (vr & 7)) * 8)) * 2;
            CP_ASYNC16(dst, Vg + (size_t)vr * TSEQ + jt * 128 + vs * 8);
        }
        CP_COMMIT();
    };

    issueKV(0);

    const __half* Qg = g_qh + ((size_t)bh * TSEQ + q0) * HSIZE;
#pragma unroll
    for (int i = 0; i < 4; ++i) {
        int f = tid + i * 256;
        int r = f >> 3, s = f & 7;
        *(uint4*)&Qs[r * 64 + ((s ^ (r & 7)) * 8)] =
            *(const uint4*)(Qg + (size_t)r * HSIZE + s * 8);
    }
    __syncthreads();

    uint32_t qa[4][4];
#pragma unroll
    for (int kb = 0; kb < 4; ++kb) {
        qa[kb][0] = *(const uint32_t*)&Qs[(mb + g) * 64 + (((2 * kb) ^ g) * 8) + 2 * t];
        qa[kb][1] = *(const uint32_t*)&Qs[(mb + g + 8) * 64 + (((2 * kb) ^ g) * 8) + 2 * t];
        qa[kb][2] = *(const uint32_t*)&Qs[(mb + g) * 64 + (((2 * kb + 1) ^ g) * 8) + 2 * t];
        qa[kb][3] = *(const uint32_t*)&Qs[(mb + g + 8) * 64 + (((2 * kb + 1) ^ g) * 8) + 2 * t];
    }

    float o[8][4];
#pragma unroll
    for (int nt = 0; nt < 8; ++nt)
#pragma unroll
        for (int j = 0; j < 4; ++j) o[nt][j] = 0.f;
    float m0 = -INFINITY, m1 = -INFINITY, l0 = 0.f, l1 = 0.f;

    const int row0 = q0 + mb + g;
    const int row1 = row0 + 8;

    for (int jt = 0; jt <= qb; ++jt) {
        CP_WAIT(0);
        __syncthreads();
        if (jt < qb) issueKV(jt + 1);

        const __half* Ks = asm_ + AQP_H + (jt & 1) * KV_H;
        const __half* Vs = Ks + AK_H;

#pragma unroll 1
        for (int hf = 0; hf < 2; ++hf) {
            // S = Q K^T over 64 keys of this half
            float s[8][4];
#pragma unroll
            for (int nt = 0; nt < 8; ++nt)
#pragma unroll
                for (int j = 0; j < 4; ++j) s[nt][j] = 0.f;
#pragma unroll
            for (int kb = 0; kb < 4; ++kb) {
#pragma unroll
                for (int nt = 0; nt < 8; ++nt) {
                    int n = hf * 64 + nt * 8 + g;
                    uint32_t b0 = *(const uint32_t*)&Ks[n * 64 + (((2 * kb) ^ g) * 8) + 2 * t];
                    uint32_t b1 = *(const uint32_t*)&Ks[n * 64 + (((2 * kb + 1) ^ g) * 8) + 2 * t];
                    mma_f16(s[nt][0], s[nt][1], s[nt][2], s[nt][3],
                            qa[kb][0], qa[kb][1], qa[kb][2], qa[kb][3], b0, b1);
                }
            }

            // causal mask (diagonal tile only)
            if (jt == qb) {
#pragma unroll
                for (int nt = 0; nt < 8; ++nt) {
                    int col = jt * 128 + hf * 64 + nt * 8 + 2 * t;
                    if (col > row0)     s[nt][0] = -INFINITY;
                    if (col + 1 > row0) s[nt][1] = -INFINITY;
                    if (col > row1)     s[nt][2] = -INFINITY;
                    if (col + 1 > row1) s[nt][3] = -INFINITY;
                }
            }

            // online softmax for this half
            float mx0 = -INFINITY, mx1 = -INFINITY;
#pragma unroll
            for (int nt = 0; nt < 8; ++nt) {
                mx0 = fmaxf(mx0, fmaxf(s[nt][0], s[nt][1]));
                mx1 = fmaxf(mx1, fmaxf(s[nt][2], s[nt][3]));
            }
            mx0 = fmaxf(mx0, __shfl_xor_sync(0xffffffffu, mx0, 1));
            mx0 = fmaxf(mx0, __shfl_xor_sync(0xffffffffu, mx0, 2));
            mx1 = fmaxf(mx1, __shfl_xor_sync(0xffffffffu, mx1, 1));
            mx1 = fmaxf(mx1, __shfl_xor_sync(0xffffffffu, mx1, 2));
            float nm0 = fmaxf(m0, mx0), nm1 = fmaxf(m1, mx1);
            float cr0 = __expf(m0 - nm0), cr1 = __expf(m1 - nm1);
            l0 *= cr0; l1 *= cr1;
#pragma unroll
            for (int nt = 0; nt < 8; ++nt) {
                o[nt][0] *= cr0; o[nt][1] *= cr0;
                o[nt][2] *= cr1; o[nt][3] *= cr1;
            }
            float s0 = 0.f, s1 = 0.f;
#pragma unroll
            for (int nt = 0; nt < 8; ++nt) {
                float p00 = __expf(s[nt][0] - nm0);
                float p01 = __expf(s[nt][1] - nm0);
                float p10 = __expf(s[nt][2] - nm1);
                float p11 = __expf(s[nt][3] - nm1);
                s0 += p00 + p01; s1 += p10 + p11;
                int seg = hf * 8 + nt;
                *(__half2*)&Ps[(mb + g) * 128 + ((seg ^ g) * 8) + 2 * t] =
                    __floats2half2_rn(p00, p01);
                *(__half2*)&Ps[(mb + g + 8) * 128 + ((seg ^ g) * 8) + 2 * t] =
                    __floats2half2_rn(p10, p11);
            }
            s0 += __shfl_xor_sync(0xffffffffu, s0, 1);
            s0 += __shfl_xor_sync(0xffffffffu, s0, 2);
            s1 += __shfl_xor_sync(0xffffffffu, s1, 1);
            s1 += __shfl_xor_sync(0xffffffffu, s1, 2);
            l0 += s0; l1 += s1;
            m0 = nm0; m1 = nm1;
            __syncwarp();

            // O += P(half) V(half): kb2 = hf*4 .. hf*4+3
#pragma unroll
            for (int kb = 0; kb < 4; ++kb) {
                int kb2 = hf * 4 + kb;
                uint32_t pa0 = *(const uint32_t*)&Ps[(mb + g) * 128 + (((2 * kb2) ^ g) * 8) + 2 * t];
                uint32_t pa1 = *(const uint32_t*)&Ps[(mb + g + 8) * 128 + (((2 * kb2) ^ g) * 8) + 2 * t];
                uint32_t pa2 = *(const uint32_t*)&Ps[(mb + g) * 128 + (((2 * kb2 + 1) ^ g) * 8) + 2 * t];
                uint32_t pa3 = *(const uint32_t*)&Ps[(mb + g + 8) * 128 + (((2 * kb2 + 1) ^ g) * 8) + 2 * t];
#pragma unroll
                for (int nt = 0; nt < 8; ++nt) {
                    int n = nt * 8 + g;
                    uint32_t b0 = *(const uint32_t*)&Vs[n * 128 + (((2 * kb2) ^ g) * 8) + 2 * t];
                    uint32_t b1 = *(const uint32_t*)&Vs[n * 128 + (((2 * kb2 + 1) ^ g) * 8) + 2 * t];
                    mma_f16(o[nt][0], o[nt][1], o[nt][2], o[nt][3],
                            pa0, pa1, pa2, pa3, b0, b1);
                }
            }
            __syncwarp();
        }
    }

    const int b = bh >> 4, h = bh & 15;
    const float inv0 = 1.f / l0, inv1 = 1.f / l1;
    __half* O0 = g_ah + ((size_t)(b * TSEQ) + row0) * CEMB + h * HSIZE;
    __half* O1 = g_ah + ((size_t)(b * TSEQ) + row1) * CEMB + h * HSIZE;
#pragma unroll
    for (int nt = 0; nt < 8; ++nt) {
        int d = nt * 8 + 2 * t;
        *(__half2*)(O0 + d) = __floats2half2_rn(o[nt][0] * inv0, o[nt][1] * inv0);
        *(__half2*)(O1 + d) = __floats2half2_rn(o[nt][2] * inv1, o[nt][3] * inv1);
    }
}

// ---------------------------------------------------------------------------
extern "C" void kernel_launch(void* const* d_in, const int* in_sizes, int n_in,
                              void* d_out, int out_size)
{
    const float* x      = (const float*)d_in[0];
    const float* w_qkv  = (const float*)d_in[1];
    const float* w_proj = (const float*)d_in[2];
    const float* b_proj = (const float*)d_in[3];
    float* out = (float*)d_out;

    __half *xh = nullptr, *ah = nullptr, *wtq = nullptr, *wtp = nullptr;
    cudaGetSymbolAddress((void**)&xh,  g_xh);
    cudaGetSymbolAddress((void**)&ah,  g_ah);
    cudaGetSymbolAddress((void**)&wtq, g_wtq);
    cudaGetSymbolAddress((void**)&wtp, g_wtp);

    const int ATTN_SMEM = (AQP_H + 2 * KV_H) * 2;       // 98304
    const int GEMM_SMEM = GSTAGES * GST_H * 2;          // 98304
    cudaFuncSetAttribute(attn_h, cudaFuncAttributeMaxDynamicSharedMemorySize, ATTN_SMEM);
    cudaFuncSetAttribute(gemm_h, cudaFuncAttributeMaxDynamicSharedMemorySize, GEMM_SMEM);

    // 0) convert x, transpose weights (K-major, half)
    cvt_x<<<MROWS * CEMB / (256 * 8), 256>>>(x, xh);
    transpose_h<<<dim3(3 * CEMB / 32, CEMB / 32), dim3(32, 8)>>>(w_qkv, wtq, CEMB, 3 * CEMB);
    transpose_h<<<dim3(CEMB / 32, CEMB / 32), dim3(32, 8)>>>(w_proj, wtp, CEMB, CEMB);

    // 1) QKV GEMM (fp16 mma, cp.async, 2 CTA/SM) + head-major scatter
    gemm_h<<<dim3(3 * CEMB / 128, MROWS / 128), 256, GEMM_SMEM>>>(
        xh, wtq, nullptr, nullptr, MROWS, 3 * CEMB, CEMB, 0);

    // 2) Causal flash attention (fp16 mma, 2 CTA/SM, 64-key halves)
    attn_h<<<dim3(TSEQ / 128, BATCH * NHEAD), 256, ATTN_SMEM>>>();

    // 3) Output projection + bias (fp16 mma, fp32 out)
    gemm_h<<<dim3(CEMB / 128, MROWS / 128), 256, GEMM_SMEM>>>(
        ah, wtp, b_proj, out, MROWS, CEMB, CEMB, 1);
}

// round 13
// speedup vs baseline: 1.0155x; 1.0155x over previous
#include <cuda_runtime.h>
#include <cuda_fp16.h>
#include <math.h>
#include <stdint.h>

// Problem constants
#define BATCH   4
#define TSEQ    2048
#define NHEAD   16
#define HSIZE   64
#define CEMB    1024
#define MROWS   (BATCH*TSEQ)   // 8192

// Scratch (device globals; fp16 operands, fp32 accum everywhere)
__device__ __half g_xh [(size_t)MROWS * CEMB];
__device__ __half g_qh [(size_t)BATCH * NHEAD * TSEQ * HSIZE]; // [B,H,T,D], q pre-scaled
__device__ __half g_kh [(size_t)BATCH * NHEAD * TSEQ * HSIZE]; // [B,H,T,D]
__device__ __half g_vh [(size_t)BATCH * NHEAD * TSEQ * HSIZE]; // [B,H,D,T] (transposed)
__device__ __half g_ah [(size_t)MROWS * CEMB];
__device__ __half g_wtq[(size_t)3 * CEMB * CEMB];              // [3C][C] K-major
__device__ __half g_wtp[(size_t)CEMB * CEMB];                  // [C][C]  K-major

// ---------------------------------------------------------------------------
// helpers
// ---------------------------------------------------------------------------
__device__ __forceinline__ void mma_f16(float& c0, float& c1, float& c2, float& c3,
                                        uint32_t a0, uint32_t a1, uint32_t a2, uint32_t a3,
                                        uint32_t b0, uint32_t b1) {
    asm volatile("mma.sync.aligned.m16n8k16.row.col.f32.f16.f16.f32 "
                 "{%0,%1,%2,%3}, {%4,%5,%6,%7}, {%8,%9}, {%0,%1,%2,%3};"
                 : "+f"(c0), "+f"(c1), "+f"(c2), "+f"(c3)
                 : "r"(a0), "r"(a1), "r"(a2), "r"(a3), "r"(b0), "r"(b1));
}
__device__ __forceinline__ uint32_t h2u(__half2 h) { return *(uint32_t*)&h; }
__device__ __forceinline__ uint32_t smem_u32(const void* p) {
    uint32_t a;
    asm("{ .reg .u64 t; cvta.to.shared.u64 t, %1; cvt.u32.u64 %0, t; }" : "=r"(a) : "l"(p));
    return a;
}
#define CP_ASYNC16(dst, src) \
    asm volatile("cp.async.cg.shared.global [%0], [%1], 16;" :: "r"(dst), "l"(src))
#define CP_COMMIT()  asm volatile("cp.async.commit_group;" ::)
#define CP_WAIT(n)   asm volatile("cp.async.wait_group %0;" :: "n"(n))

// ---------------------------------------------------------------------------
// x -> half
// ---------------------------------------------------------------------------
__global__ __launch_bounds__(256) void cvt_x(const float* __restrict__ in,
                                             __half* __restrict__ out)
{
    size_t i = ((size_t)blockIdx.x * 256 + threadIdx.x) * 8;
    float4 v0 = *(const float4*)(in + i);
    float4 v1 = *(const float4*)(in + i + 4);
    uint4 u = {h2u(__floats2half2_rn(v0.x, v0.y)), h2u(__floats2half2_rn(v0.z, v0.w)),
               h2u(__floats2half2_rn(v1.x, v1.y)), h2u(__floats2half2_rn(v1.z, v1.w))};
    *(uint4*)(out + i) = u;
}

// ---------------------------------------------------------------------------
// Weight transpose fp32 [R][C] -> half [C][R]
// ---------------------------------------------------------------------------
__global__ __launch_bounds__(256) void transpose_h(const float* __restrict__ in,
                                                   __half* __restrict__ out, int R, int C)
{
    __shared__ float t[32][33];
    int bx = blockIdx.x * 32, by = blockIdx.y * 32;
#pragma unroll
    for (int i = 0; i < 32; i += 8)
        t[threadIdx.y + i][threadIdx.x] = in[(size_t)(by + threadIdx.y + i) * C + bx + threadIdx.x];
    __syncthreads();
#pragma unroll
    for (int i = 0; i < 32; i += 8)
        out[(size_t)(bx + threadIdx.y + i) * R + by + threadIdx.x] =
            __float2half_rn(t[threadIdx.x][threadIdx.y + i]);
}

// ---------------------------------------------------------------------------
// fp16 GEMM (round-11 version, measured best): 128x128 tile, cp.async 3-stage,
// 2 CTAs/SM.
// ---------------------------------------------------------------------------
#define GA_H   (128 * 64)
#define GB_H   (128 * 64)
#define GST_H  (GA_H + GB_H)      // 32KB per stage
#define GSTAGES 3
__global__ __launch_bounds__(256, 2) void gemm_h(
    const __half* __restrict__ A, const __half* __restrict__ Bt,
    const float* __restrict__ bias, float* __restrict__ C,
    int M, int N, int K, int mode)
{
    extern __shared__ __align__(16) __half hsm[];
    const uint32_t sb = smem_u32(hsm);

    const int tid  = threadIdx.x;
    const int wid  = tid >> 5;
    const int lane = tid & 31;
    const int g    = lane >> 2;
    const int t    = lane & 3;
    const int wm   = wid & 3;
    const int wn   = wid >> 2;
    const int m0 = blockIdx.y * 128;
    const int n0 = blockIdx.x * 128;

    const int lrA = tid >> 3;
    const int lsA = tid & 7;

    float c[2][8][4];
#pragma unroll
    for (int mt = 0; mt < 2; ++mt)
#pragma unroll
        for (int nt = 0; nt < 8; ++nt)
#pragma unroll
            for (int j = 0; j < 4; ++j) c[mt][nt][j] = 0.f;

    auto issue = [&](int s) {
        const int base = (s % GSTAGES) * GST_H;
        const int koff = (s << 6) + lsA * 8;
#pragma unroll
        for (int i = 0; i < 4; ++i) {
            int r = lrA + i * 32;
            uint32_t dst = sb + (uint32_t)(base + r * 64 + ((lsA ^ (r & 7)) * 8)) * 2;
            CP_ASYNC16(dst, A + (size_t)(m0 + r) * K + koff);
        }
#pragma unroll
        for (int i = 0; i < 4; ++i) {
            int r = lrA + i * 32;
            uint32_t dst = sb + (uint32_t)(base + GA_H + r * 64 + ((lsA ^ (r & 7)) * 8)) * 2;
            CP_ASYNC16(dst, Bt + (size_t)(n0 + r) * K + koff);
        }
        CP_COMMIT();
    };

    const int KS = K >> 6;
    issue(0);
    issue(1);

#pragma unroll 1
    for (int s = 0; s < KS; ++s) {
        if (s + 1 < KS) { CP_WAIT(1); } else { CP_WAIT(0); }
        __syncthreads();
        if (s + 2 < KS) issue(s + 2);

        const __half* As = hsm + (s % GSTAGES) * GST_H;
        const __half* Bs = As + GA_H;

#pragma unroll
        for (int kt = 0; kt < 4; ++kt) {
            uint32_t bf[8][2];
#pragma unroll
            for (int nt = 0; nt < 8; ++nt) {
                int n = wn * 64 + nt * 8 + g;
                bf[nt][0] = *(const uint32_t*)&Bs[n * 64 + (((2 * kt) ^ g) * 8) + 2 * t];
                bf[nt][1] = *(const uint32_t*)&Bs[n * 64 + (((2 * kt + 1) ^ g) * 8) + 2 * t];
            }
#pragma unroll
            for (int mt = 0; mt < 2; ++mt) {
                int mb = wm * 32 + mt * 16;
                uint32_t a0 = *(const uint32_t*)&As[(mb + g) * 64 + (((2 * kt) ^ g) * 8) + 2 * t];
                uint32_t a1 = *(const uint32_t*)&As[(mb + g + 8) * 64 + (((2 * kt) ^ g) * 8) + 2 * t];
                uint32_t a2 = *(const uint32_t*)&As[(mb + g) * 64 + (((2 * kt + 1) ^ g) * 8) + 2 * t];
                uint32_t a3 = *(const uint32_t*)&As[(mb + g + 8) * 64 + (((2 * kt + 1) ^ g) * 8) + 2 * t];
#pragma unroll
                for (int nt = 0; nt < 8; ++nt)
                    mma_f16(c[mt][nt][0], c[mt][nt][1], c[mt][nt][2], c[mt][nt][3],
                            a0, a1, a2, a3, bf[nt][0], bf[nt][1]);
            }
        }
    }

    const int nbase = n0 + wn * 64;
    if (mode == 0) {
        const int which = nbase >> 10;
        const int h = (nbase & 1023) >> 6;
#pragma unroll
        for (int mt = 0; mt < 2; ++mt) {
            int r0 = m0 + wm * 32 + mt * 16 + g;
            int bb0 = r0 >> 11, tt0 = r0 & (TSEQ - 1);
            int r1 = r0 + 8;
            int bb1 = r1 >> 11, tt1 = r1 & (TSEQ - 1);
            if (which == 2) {
                __half* base0 = g_vh + ((size_t)(bb0 * NHEAD + h)) * HSIZE * TSEQ;
                __half* base1 = g_vh + ((size_t)(bb1 * NHEAD + h)) * HSIZE * TSEQ;
#pragma unroll
                for (int nt = 0; nt < 8; ++nt) {
                    int d = nt * 8 + 2 * t;
                    base0[(size_t)d * TSEQ + tt0]       = __float2half_rn(c[mt][nt][0]);
                    base0[(size_t)(d + 1) * TSEQ + tt0] = __float2half_rn(c[mt][nt][1]);
                    base1[(size_t)d * TSEQ + tt1]       = __float2half_rn(c[mt][nt][2]);
                    base1[(size_t)(d + 1) * TSEQ + tt1] = __float2half_rn(c[mt][nt][3]);
                }
            } else {
                const float sc = (which == 0) ? 0.125f : 1.0f;
                __half* base = (which == 0) ? g_qh : g_kh;
                __half* d0 = base + (((size_t)(bb0 * NHEAD + h) * TSEQ) + tt0) * HSIZE;
                __half* d1 = base + (((size_t)(bb1 * NHEAD + h) * TSEQ) + tt1) * HSIZE;
#pragma unroll
                for (int nt = 0; nt < 8; ++nt) {
                    int d = nt * 8 + 2 * t;
                    *(__half2*)(d0 + d) = __floats2half2_rn(c[mt][nt][0] * sc, c[mt][nt][1] * sc);
                    *(__half2*)(d1 + d) = __floats2half2_rn(c[mt][nt][2] * sc, c[mt][nt][3] * sc);
                }
            }
        }
    } else {
#pragma unroll
        for (int mt = 0; mt < 2; ++mt) {
            int r0 = m0 + wm * 32 + mt * 16 + g;
#pragma unroll
            for (int nt = 0; nt < 8; ++nt) {
                int n = nbase + nt * 8 + 2 * t;
                float2 bv = *(const float2*)(bias + n);
                float2 v0 = {c[mt][nt][0] + bv.x, c[mt][nt][1] + bv.y};
                float2 v1 = {c[mt][nt][2] + bv.x, c[mt][nt][3] + bv.y};
                *(float2*)(C + (size_t)r0 * N + n) = v0;
                *(float2*)(C + (size_t)(r0 + 8) * N + n) = v1;
            }
        }
    }
}

// ---------------------------------------------------------------------------
// fp16 causal flash attention: 128-THREAD CTAs (4 warps, 64 queries) so TWO
// CTAs co-reside per SM with the full round-11 warp structure (s[16][4],
// ONE softmax per 128-key tile). cp.async double-buffered KV.
// Smem (halfs): QP 64x128 (16KB; Q stage cols 0..63, then P),
//               2 x { K 128x64 (16KB), V 64x128 (16KB) } = 64KB. Total 80KB.
// Only the last key-tile crosses the diagonal (64-aligned q0) -> mask there.
// ---------------------------------------------------------------------------
#define AQP_H (64 * 128)
#define AK_H  (128 * 64)
#define KV_H  (AK_H + 64 * 128)   // 16384 halfs per buffer
__global__ __launch_bounds__(128) void attn_h()
{
    extern __shared__ __align__(16) __half asm_[];
    __half* Qs = asm_;
    __half* Ps = Qs;
    const uint32_t sb = smem_u32(asm_);

    const int tid  = threadIdx.x;
    const int wid  = tid >> 5;          // 0..3
    const int lane = tid & 31;
    const int g    = lane >> 2;
    const int t    = lane & 3;
    const int mb   = wid * 16;          // warp's query-row base (0..48)
    const int bh   = blockIdx.y;
    const int qi   = gridDim.x - 1 - blockIdx.x;   // heavy CTAs first
    const int q0   = qi * 64;
    const int jmax = (q0 + 64 + 127) >> 7;         // 128-key tiles to cover [0, q0+64)

    const __half* Kg = g_kh + (size_t)bh * TSEQ * HSIZE;
    const __half* Vg = g_vh + (size_t)bh * HSIZE * TSEQ;

    auto issueKV = [&](int jt) {
        const int base = AQP_H + (jt & 1) * KV_H;
#pragma unroll
        for (int i = 0; i < 8; ++i) {
            int f = tid + i * 128;
            int kr = f >> 3, ks = f & 7;
            uint32_t dst = sb + (uint32_t)(base + kr * 64 + ((ks ^ (kr & 7)) * 8)) * 2;
            CP_ASYNC16(dst, Kg + (size_t)(jt * 128 + kr) * HSIZE + ks * 8);
        }
#pragma unroll
        for (int i = 0; i < 8; ++i) {
            int f = tid + i * 128;
            int vr = f >> 4, vs = f & 15;
            uint32_t dst = sb + (uint32_t)(base + AK_H + vr * 128 + ((vs ^ (vr & 7)) * 8)) * 2;
            CP_ASYNC16(dst, Vg + (size_t)vr * TSEQ + jt * 128 + vs * 8);
        }
        CP_COMMIT();
    };

    issueKV(0);

    // stage Q tile [64][64] halfs
    const __half* Qg = g_qh + ((size_t)bh * TSEQ + q0) * HSIZE;
#pragma unroll
    for (int i = 0; i < 4; ++i) {
        int f = tid + i * 128;
        int r = f >> 3, s = f & 7;
        *(uint4*)&Qs[r * 64 + ((s ^ (r & 7)) * 8)] =
            *(const uint4*)(Qg + (size_t)r * HSIZE + s * 8);
    }
    __syncthreads();

    uint32_t qa[4][4];
#pragma unroll
    for (int kb = 0; kb < 4; ++kb) {
        qa[kb][0] = *(const uint32_t*)&Qs[(mb + g) * 64 + (((2 * kb) ^ g) * 8) + 2 * t];
        qa[kb][1] = *(const uint32_t*)&Qs[(mb + g + 8) * 64 + (((2 * kb) ^ g) * 8) + 2 * t];
        qa[kb][2] = *(const uint32_t*)&Qs[(mb + g) * 64 + (((2 * kb + 1) ^ g) * 8) + 2 * t];
        qa[kb][3] = *(const uint32_t*)&Qs[(mb + g + 8) * 64 + (((2 * kb + 1) ^ g) * 8) + 2 * t];
    }

    float o[8][4];
#pragma unroll
    for (int nt = 0; nt < 8; ++nt)
#pragma unroll
        for (int j = 0; j < 4; ++j) o[nt][j] = 0.f;
    float m0 = -INFINITY, m1 = -INFINITY, l0 = 0.f, l1 = 0.f;

    const int row0 = q0 + mb + g;
    const int row1 = row0 + 8;

    for (int jt = 0; jt < jmax; ++jt) {
        CP_WAIT(0);
        __syncthreads();
        if (jt + 1 < jmax) issueKV(jt + 1);

        const __half* Ks = asm_ + AQP_H + (jt & 1) * KV_H;
        const __half* Vs = Ks + AK_H;

        // S = Q K^T : 16 rows x 128 keys per warp
        float s[16][4];
#pragma unroll
        for (int nt = 0; nt < 16; ++nt)
#pragma unroll
            for (int j = 0; j < 4; ++j) s[nt][j] = 0.f;
#pragma unroll
        for (int kb = 0; kb < 4; ++kb) {
#pragma unroll
            for (int nt = 0; nt < 16; ++nt) {
                int n = nt * 8 + g;
                uint32_t b0 = *(const uint32_t*)&Ks[n * 64 + (((2 * kb) ^ g) * 8) + 2 * t];
                uint32_t b1 = *(const uint32_t*)&Ks[n * 64 + (((2 * kb + 1) ^ g) * 8) + 2 * t];
                mma_f16(s[nt][0], s[nt][1], s[nt][2], s[nt][3],
                        qa[kb][0], qa[kb][1], qa[kb][2], qa[kb][3], b0, b1);
            }
        }

        // causal mask (last tile only; earlier tiles fully below diagonal)
        if (jt == jmax - 1) {
#pragma unroll
            for (int nt = 0; nt < 16; ++nt) {
                int col = jt * 128 + nt * 8 + 2 * t;
                if (col > row0)     s[nt][0] = -INFINITY;
                if (col + 1 > row0) s[nt][1] = -INFINITY;
                if (col > row1)     s[nt][2] = -INFINITY;
                if (col + 1 > row1) s[nt][3] = -INFINITY;
            }
        }

        // online softmax (fp32), once per 128-key tile
        float mx0 = -INFINITY, mx1 = -INFINITY;
#pragma unroll
        for (int nt = 0; nt < 16; ++nt) {
            mx0 = fmaxf(mx0, fmaxf(s[nt][0], s[nt][1]));
            mx1 = fmaxf(mx1, fmaxf(s[nt][2], s[nt][3]));
        }
        mx0 = fmaxf(mx0, __shfl_xor_sync(0xffffffffu, mx0, 1));
        mx0 = fmaxf(mx0, __shfl_xor_sync(0xffffffffu, mx0, 2));
        mx1 = fmaxf(mx1, __shfl_xor_sync(0xffffffffu, mx1, 1));
        mx1 = fmaxf(mx1, __shfl_xor_sync(0xffffffffu, mx1, 2));
        float nm0 = fmaxf(m0, mx0), nm1 = fmaxf(m1, mx1);
        float cr0 = __expf(m0 - nm0), cr1 = __expf(m1 - nm1);
        l0 *= cr0; l1 *= cr1;
#pragma unroll
        for (int nt = 0; nt < 8; ++nt) {
            o[nt][0] *= cr0; o[nt][1] *= cr0;
            o[nt][2] *= cr1; o[nt][3] *= cr1;
        }
        float s0 = 0.f, s1 = 0.f;
#pragma unroll
        for (int nt = 0; nt < 16; ++nt) {
            float p00 = __expf(s[nt][0] - nm0);
            float p01 = __expf(s[nt][1] - nm0);
            float p10 = __expf(s[nt][2] - nm1);
            float p11 = __expf(s[nt][3] - nm1);
            s0 += p00 + p01; s1 += p10 + p11;
            *(__half2*)&Ps[(mb + g) * 128 + ((nt ^ g) * 8) + 2 * t] =
                __floats2half2_rn(p00, p01);
            *(__half2*)&Ps[(mb + g + 8) * 128 + ((nt ^ g) * 8) + 2 * t] =
                __floats2half2_rn(p10, p11);
        }
        s0 += __shfl_xor_sync(0xffffffffu, s0, 1);
        s0 += __shfl_xor_sync(0xffffffffu, s0, 2);
        s1 += __shfl_xor_sync(0xffffffffu, s1, 1);
        s1 += __shfl_xor_sync(0xffffffffu, s1, 2);
        l0 += s0; l1 += s1;
        m0 = nm0; m1 = nm1;
        __syncwarp();

        // O += P V
#pragma unroll
        for (int kb = 0; kb < 8; ++kb) {
            uint32_t pa0 = *(const uint32_t*)&Ps[(mb + g) * 128 + (((2 * kb) ^ g) * 8) + 2 * t];
            uint32_t pa1 = *(const uint32_t*)&Ps[(mb + g + 8) * 128 + (((2 * kb) ^ g) * 8) + 2 * t];
            uint32_t pa2 = *(const uint32_t*)&Ps[(mb + g) * 128 + (((2 * kb + 1) ^ g) * 8) + 2 * t];
            uint32_t pa3 = *(const uint32_t*)&Ps[(mb + g + 8) * 128 + (((2 * kb + 1) ^ g) * 8) + 2 * t];
#pragma unroll
            for (int nt = 0; nt < 8; ++nt) {
                int n = nt * 8 + g;
                uint32_t b0 = *(const uint32_t*)&Vs[n * 128 + (((2 * kb) ^ g) * 8) + 2 * t];
                uint32_t b1 = *(const uint32_t*)&Vs[n * 128 + (((2 * kb + 1) ^ g) * 8) + 2 * t];
                mma_f16(o[nt][0], o[nt][1], o[nt][2], o[nt][3],
                        pa0, pa1, pa2, pa3, b0, b1);
            }
        }
    }

    const int b = bh >> 4, h = bh & 15;
    const float inv0 = 1.f / l0, inv1 = 1.f / l1;
    __half* O0 = g_ah + ((size_t)(b * TSEQ) + row0) * CEMB + h * HSIZE;
    __half* O1 = g_ah + ((size_t)(b * TSEQ) + row1) * CEMB + h * HSIZE;
#pragma unroll
    for (int nt = 0; nt < 8; ++nt) {
        int d = nt * 8 + 2 * t;
        *(__half2*)(O0 + d) = __floats2half2_rn(o[nt][0] * inv0, o[nt][1] * inv0);
        *(__half2*)(O1 + d) = __floats2half2_rn(o[nt][2] * inv1, o[nt][3] * inv1);
    }
}

// ---------------------------------------------------------------------------
extern "C" void kernel_launch(void* const* d_in, const int* in_sizes, int n_in,
                              void* d_out, int out_size)
{
    const float* x      = (const float*)d_in[0];
    const float* w_qkv  = (const float*)d_in[1];
    const float* w_proj = (const float*)d_in[2];
    const float* b_proj = (const float*)d_in[3];
    float* out = (float*)d_out;

    __half *xh = nullptr, *ah = nullptr, *wtq = nullptr, *wtp = nullptr;
    cudaGetSymbolAddress((void**)&xh,  g_xh);
    cudaGetSymbolAddress((void**)&ah,  g_ah);
    cudaGetSymbolAddress((void**)&wtq, g_wtq);
    cudaGetSymbolAddress((void**)&wtp, g_wtp);

    const int ATTN_SMEM = (AQP_H + 2 * KV_H) * 2;       // 81920
    const int GEMM_SMEM = GSTAGES * GST_H * 2;          // 98304
    cudaFuncSetAttribute(attn_h, cudaFuncAttributeMaxDynamicSharedMemorySize, ATTN_SMEM);
    cudaFuncSetAttribute(gemm_h, cudaFuncAttributeMaxDynamicSharedMemorySize, GEMM_SMEM);

    // 0) convert x, transpose weights (K-major, half)
    cvt_x<<<MROWS * CEMB / (256 * 8), 256>>>(x, xh);
    transpose_h<<<dim3(3 * CEMB / 32, CEMB / 32), dim3(32, 8)>>>(w_qkv, wtq, CEMB, 3 * CEMB);
    transpose_h<<<dim3(CEMB / 32, CEMB / 32), dim3(32, 8)>>>(w_proj, wtp, CEMB, CEMB);

    // 1) QKV GEMM (fp16 mma, cp.async, 2 CTA/SM) + head-major scatter
    gemm_h<<<dim3(3 * CEMB / 128, MROWS / 128), 256, GEMM_SMEM>>>(
        xh, wtq, nullptr, nullptr, MROWS, 3 * CEMB, CEMB, 0);

    // 2) Causal flash attention (fp16 mma, 128-thread CTAs, 2 CTA/SM)
    attn_h<<<dim3(TSEQ / 64, BATCH * NHEAD), 128, ATTN_SMEM>>>();

    // 3) Output projection + bias (fp16 mma, fp32 out)
    gemm_h<<<dim3(CEMB / 128, MROWS / 128), 256, GEMM_SMEM>>>(
        ah, wtp, b_proj, out, MROWS, CEMB, CEMB, 1);
}

// round 14
// speedup vs baseline: 1.1271x; 1.1099x over previous
#include <cuda_runtime.h>
#include <cuda_fp16.h>
#include <math.h>
#include <stdint.h>

// Problem constants
#define BATCH   4
#define TSEQ    2048
#define NHEAD   16
#define HSIZE   64
#define CEMB    1024
#define MROWS   (BATCH*TSEQ)   // 8192

// Scratch (device globals; fp16 operands, fp32 accum everywhere)
__device__ __half g_xh [(size_t)MROWS * CEMB];
__device__ __half g_qh [(size_t)BATCH * NHEAD * TSEQ * HSIZE]; // [B,H,T,D], q pre-scaled
__device__ __half g_kh [(size_t)BATCH * NHEAD * TSEQ * HSIZE]; // [B,H,T,D]
__device__ __half g_vh [(size_t)BATCH * NHEAD * TSEQ * HSIZE]; // [B,H,D,T] (transposed)
__device__ __half g_ah [(size_t)MROWS * CEMB];
__device__ __half g_wtq[(size_t)3 * CEMB * CEMB];              // [3C][C] K-major
__device__ __half g_wtp[(size_t)CEMB * CEMB];                  // [C][C]  K-major

// ---------------------------------------------------------------------------
// helpers
// ---------------------------------------------------------------------------
__device__ __forceinline__ void mma_f16(float& c0, float& c1, float& c2, float& c3,
                                        uint32_t a0, uint32_t a1, uint32_t a2, uint32_t a3,
                                        uint32_t b0, uint32_t b1) {
    asm volatile("mma.sync.aligned.m16n8k16.row.col.f32.f16.f16.f32 "
                 "{%0,%1,%2,%3}, {%4,%5,%6,%7}, {%8,%9}, {%0,%1,%2,%3};"
                 : "+f"(c0), "+f"(c1), "+f"(c2), "+f"(c3)
                 : "r"(a0), "r"(a1), "r"(a2), "r"(a3), "r"(b0), "r"(b1));
}
__device__ __forceinline__ void ldsm_x4(uint32_t& r0, uint32_t& r1, uint32_t& r2,
                                        uint32_t& r3, uint32_t addr) {
    asm volatile("ldmatrix.sync.aligned.m8n8.x4.shared.b16 {%0,%1,%2,%3}, [%4];"
                 : "=r"(r0), "=r"(r1), "=r"(r2), "=r"(r3) : "r"(addr));
}
__device__ __forceinline__ uint32_t h2u(__half2 h) { return *(uint32_t*)&h; }
__device__ __forceinline__ uint32_t smem_u32(const void* p) {
    uint32_t a;
    asm("{ .reg .u64 t; cvta.to.shared.u64 t, %1; cvt.u32.u64 %0, t; }" : "=r"(a) : "l"(p));
    return a;
}
#define CP_ASYNC16(dst, src) \
    asm volatile("cp.async.cg.shared.global [%0], [%1], 16;" :: "r"(dst), "l"(src))
#define CP_COMMIT()  asm volatile("cp.async.commit_group;" ::)
#define CP_WAIT(n)   asm volatile("cp.async.wait_group %0;" :: "n"(n))

// ---------------------------------------------------------------------------
// x -> half
// ---------------------------------------------------------------------------
__global__ __launch_bounds__(256) void cvt_x(const float* __restrict__ in,
                                             __half* __restrict__ out)
{
    size_t i = ((size_t)blockIdx.x * 256 + threadIdx.x) * 8;
    float4 v0 = *(const float4*)(in + i);
    float4 v1 = *(const float4*)(in + i + 4);
    uint4 u = {h2u(__floats2half2_rn(v0.x, v0.y)), h2u(__floats2half2_rn(v0.z, v0.w)),
               h2u(__floats2half2_rn(v1.x, v1.y)), h2u(__floats2half2_rn(v1.z, v1.w))};
    *(uint4*)(out + i) = u;
}

// ---------------------------------------------------------------------------
// Weight transpose fp32 [R][C] -> half [C][R]
// ---------------------------------------------------------------------------
__global__ __launch_bounds__(256) void transpose_h(const float* __restrict__ in,
                                                   __half* __restrict__ out, int R, int C)
{
    __shared__ float t[32][33];
    int bx = blockIdx.x * 32, by = blockIdx.y * 32;
#pragma unroll
    for (int i = 0; i < 32; i += 8)
        t[threadIdx.y + i][threadIdx.x] = in[(size_t)(by + threadIdx.y + i) * C + bx + threadIdx.x];
    __syncthreads();
#pragma unroll
    for (int i = 0; i < 32; i += 8)
        out[(size_t)(bx + threadIdx.y + i) * R + by + threadIdx.x] =
            __float2half_rn(t[threadIdx.x][threadIdx.y + i]);
}

// ---------------------------------------------------------------------------
// fp16 GEMM: 128x128 tile, cp.async 3-stage, 2 CTAs/SM, ldmatrix fragments.
// ---------------------------------------------------------------------------
#define GA_H   (128 * 64)
#define GB_H   (128 * 64)
#define GST_H  (GA_H + GB_H)      // 32KB per stage
#define GSTAGES 3
__global__ __launch_bounds__(256, 2) void gemm_h(
    const __half* __restrict__ A, const __half* __restrict__ Bt,
    const float* __restrict__ bias, float* __restrict__ C,
    int M, int N, int K, int mode)
{
    extern __shared__ __align__(16) __half hsm[];
    const uint32_t sb = smem_u32(hsm);

    const int tid  = threadIdx.x;
    const int wid  = tid >> 5;
    const int lane = tid & 31;
    const int g    = lane >> 2;
    const int t    = lane & 3;
    const int wm   = wid & 3;
    const int wn   = wid >> 2;
    const int m0 = blockIdx.y * 128;
    const int n0 = blockIdx.x * 128;

    const int lrA = tid >> 3;
    const int lsA = tid & 7;

    // ldmatrix per-thread selectors
    const int j    = lane & 7;
    const int hsel = lane >> 4;          // A: k-half selector; B: n-group selector
    const int rsel = (lane >> 3) & 1;    // A: row-block selector; B: k-half selector
    const int aRow = rsel * 8 + j;       // + m base
    const int bRow = hsel * 8 + j;       // + n base

    float c[2][8][4];
#pragma unroll
    for (int mt = 0; mt < 2; ++mt)
#pragma unroll
        for (int nt = 0; nt < 8; ++nt)
#pragma unroll
            for (int jj = 0; jj < 4; ++jj) c[mt][nt][jj] = 0.f;

    auto issue = [&](int s) {
        const int base = (s % GSTAGES) * GST_H;
        const int koff = (s << 6) + lsA * 8;
#pragma unroll
        for (int i = 0; i < 4; ++i) {
            int r = lrA + i * 32;
            uint32_t dst = sb + (uint32_t)(base + r * 64 + ((lsA ^ (r & 7)) * 8)) * 2;
            CP_ASYNC16(dst, A + (size_t)(m0 + r) * K + koff);
        }
#pragma unroll
        for (int i = 0; i < 4; ++i) {
            int r = lrA + i * 32;
            uint32_t dst = sb + (uint32_t)(base + GA_H + r * 64 + ((lsA ^ (r & 7)) * 8)) * 2;
            CP_ASYNC16(dst, Bt + (size_t)(n0 + r) * K + koff);
        }
        CP_COMMIT();
    };

    const int KS = K >> 6;
    issue(0);
    issue(1);

#pragma unroll 1
    for (int s = 0; s < KS; ++s) {
        if (s + 1 < KS) { CP_WAIT(1); } else { CP_WAIT(0); }
        __syncthreads();
        if (s + 2 < KS) issue(s + 2);

        const uint32_t stA = sb + (uint32_t)((s % GSTAGES) * GST_H) * 2;
        const uint32_t stB = stA + GA_H * 2;

#pragma unroll
        for (int kt = 0; kt < 4; ++kt) {
            uint32_t bf[8][2];
#pragma unroll
            for (int p = 0; p < 4; ++p) {
                int n = wn * 64 + p * 16 + bRow;
                int seg = (2 * kt + rsel) ^ j;
                ldsm_x4(bf[2 * p][0], bf[2 * p][1], bf[2 * p + 1][0], bf[2 * p + 1][1],
                        stB + (uint32_t)(n * 64 + seg * 8) * 2);
            }
#pragma unroll
            for (int mt = 0; mt < 2; ++mt) {
                int row = wm * 32 + mt * 16 + aRow;
                int seg = (2 * kt + hsel) ^ j;
                uint32_t a0, a1, a2, a3;
                ldsm_x4(a0, a1, a2, a3, stA + (uint32_t)(row * 64 + seg * 8) * 2);
#pragma unroll
                for (int nt = 0; nt < 8; ++nt)
                    mma_f16(c[mt][nt][0], c[mt][nt][1], c[mt][nt][2], c[mt][nt][3],
                            a0, a1, a2, a3, bf[nt][0], bf[nt][1]);
            }
        }
    }

    const int nbase = n0 + wn * 64;
    if (mode == 0) {
        const int which = nbase >> 10;
        const int h = (nbase & 1023) >> 6;
#pragma unroll
        for (int mt = 0; mt < 2; ++mt) {
            int r0 = m0 + wm * 32 + mt * 16 + g;
            int bb0 = r0 >> 11, tt0 = r0 & (TSEQ - 1);
            int r1 = r0 + 8;
            int bb1 = r1 >> 11, tt1 = r1 & (TSEQ - 1);
            if (which == 2) {
                __half* base0 = g_vh + ((size_t)(bb0 * NHEAD + h)) * HSIZE * TSEQ;
                __half* base1 = g_vh + ((size_t)(bb1 * NHEAD + h)) * HSIZE * TSEQ;
#pragma unroll
                for (int nt = 0; nt < 8; ++nt) {
                    int d = nt * 8 + 2 * t;
                    base0[(size_t)d * TSEQ + tt0]       = __float2half_rn(c[mt][nt][0]);
                    base0[(size_t)(d + 1) * TSEQ + tt0] = __float2half_rn(c[mt][nt][1]);
                    base1[(size_t)d * TSEQ + tt1]       = __float2half_rn(c[mt][nt][2]);
                    base1[(size_t)(d + 1) * TSEQ + tt1] = __float2half_rn(c[mt][nt][3]);
                }
            } else {
                const float sc = (which == 0) ? 0.125f : 1.0f;
                __half* base = (which == 0) ? g_qh : g_kh;
                __half* d0 = base + (((size_t)(bb0 * NHEAD + h) * TSEQ) + tt0) * HSIZE;
                __half* d1 = base + (((size_t)(bb1 * NHEAD + h) * TSEQ) + tt1) * HSIZE;
#pragma unroll
                for (int nt = 0; nt < 8; ++nt) {
                    int d = nt * 8 + 2 * t;
                    *(__half2*)(d0 + d) = __floats2half2_rn(c[mt][nt][0] * sc, c[mt][nt][1] * sc);
                    *(__half2*)(d1 + d) = __floats2half2_rn(c[mt][nt][2] * sc, c[mt][nt][3] * sc);
                }
            }
        }
    } else {
#pragma unroll
        for (int mt = 0; mt < 2; ++mt) {
            int r0 = m0 + wm * 32 + mt * 16 + g;
#pragma unroll
            for (int nt = 0; nt < 8; ++nt) {
                int n = nbase + nt * 8 + 2 * t;
                float2 bv = *(const float2*)(bias + n);
                float2 v0 = {c[mt][nt][0] + bv.x, c[mt][nt][1] + bv.y};
                float2 v1 = {c[mt][nt][2] + bv.x, c[mt][nt][3] + bv.y};
                *(float2*)(C + (size_t)r0 * N + n) = v0;
                *(float2*)(C + (size_t)(r0 + 8) * N + n) = v1;
            }
        }
    }
}

// ---------------------------------------------------------------------------
// fp16 causal flash attention: 128-thread CTAs (4 warps, 64 queries),
// cp.async double-buffered 128-key KV tiles, ldmatrix fragments.
// Smem (halfs): QP 64x128 (Q stage stride 64 / P stride 128), 2 x {K 128x64,
// V 64x128}. 80KB/CTA.
// ---------------------------------------------------------------------------
#define AQP_H (64 * 128)
#define AK_H  (128 * 64)
#define KV_H  (AK_H + 64 * 128)   // 16384 halfs per buffer
__global__ __launch_bounds__(128) void attn_h()
{
    extern __shared__ __align__(16) __half asm_[];
    __half* Qs = asm_;
    __half* Ps = Qs;
    const uint32_t sb = smem_u32(asm_);

    const int tid  = threadIdx.x;
    const int wid  = tid >> 5;          // 0..3
    const int lane = tid & 31;
    const int g    = lane >> 2;
    const int t    = lane & 3;
    const int mb   = wid * 16;
    const int bh   = blockIdx.y;
    const int qi   = gridDim.x - 1 - blockIdx.x;   // heavy CTAs first
    const int q0   = qi * 64;
    const int jmax = (q0 + 64 + 127) >> 7;

    // ldmatrix selectors
    const int j    = lane & 7;
    const int hsel = lane >> 4;
    const int rsel = (lane >> 3) & 1;
    const int aRow = rsel * 8 + j;
    const int bRow = hsel * 8 + j;

    const __half* Kg = g_kh + (size_t)bh * TSEQ * HSIZE;
    const __half* Vg = g_vh + (size_t)bh * HSIZE * TSEQ;

    auto issueKV = [&](int jt) {
        const int base = AQP_H + (jt & 1) * KV_H;
#pragma unroll
        for (int i = 0; i < 8; ++i) {
            int f = tid + i * 128;
            int kr = f >> 3, ks = f & 7;
            uint32_t dst = sb + (uint32_t)(base + kr * 64 + ((ks ^ (kr & 7)) * 8)) * 2;
            CP_ASYNC16(dst, Kg + (size_t)(jt * 128 + kr) * HSIZE + ks * 8);
        }
#pragma unroll
        for (int i = 0; i < 8; ++i) {
            int f = tid + i * 128;
            int vr = f >> 4, vs = f & 15;
            uint32_t dst = sb + (uint32_t)(base + AK_H + vr * 128 + ((vs ^ (vr & 7)) * 8)) * 2;
            CP_ASYNC16(dst, Vg + (size_t)vr * TSEQ + jt * 128 + vs * 8);
        }
        CP_COMMIT();
    };

    issueKV(0);

    // stage Q tile [64][64] halfs
    const __half* Qg = g_qh + ((size_t)bh * TSEQ + q0) * HSIZE;
#pragma unroll
    for (int i = 0; i < 4; ++i) {
        int f = tid + i * 128;
        int r = f >> 3, s = f & 7;
        *(uint4*)&Qs[r * 64 + ((s ^ (r & 7)) * 8)] =
            *(const uint4*)(Qg + (size_t)r * HSIZE + s * 8);
    }
    __syncthreads();

    uint32_t qa[4][4];
#pragma unroll
    for (int kb = 0; kb < 4; ++kb) {
        int row = mb + aRow;
        int seg = (2 * kb + hsel) ^ j;
        ldsm_x4(qa[kb][0], qa[kb][1], qa[kb][2], qa[kb][3],
                sb + (uint32_t)(row * 64 + seg * 8) * 2);
    }

    float o[8][4];
#pragma unroll
    for (int nt = 0; nt < 8; ++nt)
#pragma unroll
        for (int jj = 0; jj < 4; ++jj) o[nt][jj] = 0.f;
    float m0 = -INFINITY, m1 = -INFINITY, l0 = 0.f, l1 = 0.f;

    const int row0 = q0 + mb + g;
    const int row1 = row0 + 8;

    for (int jt = 0; jt < jmax; ++jt) {
        CP_WAIT(0);
        __syncthreads();
        if (jt + 1 < jmax) issueKV(jt + 1);

        const uint32_t ksb = sb + (uint32_t)(AQP_H + (jt & 1) * KV_H) * 2;
        const uint32_t vsb = ksb + AK_H * 2;

        // S = Q K^T : 16 rows x 128 keys per warp
        float s[16][4];
#pragma unroll
        for (int nt = 0; nt < 16; ++nt)
#pragma unroll
            for (int jj = 0; jj < 4; ++jj) s[nt][jj] = 0.f;
#pragma unroll
        for (int kb = 0; kb < 4; ++kb) {
            uint32_t kf[16][2];
#pragma unroll
            for (int p = 0; p < 8; ++p) {
                int n = p * 16 + bRow;
                int seg = (2 * kb + rsel) ^ j;
                ldsm_x4(kf[2 * p][0], kf[2 * p][1], kf[2 * p + 1][0], kf[2 * p + 1][1],
                        ksb + (uint32_t)(n * 64 + seg * 8) * 2);
            }
#pragma unroll
            for (int nt = 0; nt < 16; ++nt)
                mma_f16(s[nt][0], s[nt][1], s[nt][2], s[nt][3],
                        qa[kb][0], qa[kb][1], qa[kb][2], qa[kb][3],
                        kf[nt][0], kf[nt][1]);
        }

        // causal mask (last tile only)
        if (jt == jmax - 1) {
#pragma unroll
            for (int nt = 0; nt < 16; ++nt) {
                int col = jt * 128 + nt * 8 + 2 * t;
                if (col > row0)     s[nt][0] = -INFINITY;
                if (col + 1 > row0) s[nt][1] = -INFINITY;
                if (col > row1)     s[nt][2] = -INFINITY;
                if (col + 1 > row1) s[nt][3] = -INFINITY;
            }
        }

        // online softmax (fp32)
        float mx0 = -INFINITY, mx1 = -INFINITY;
#pragma unroll
        for (int nt = 0; nt < 16; ++nt) {
            mx0 = fmaxf(mx0, fmaxf(s[nt][0], s[nt][1]));
            mx1 = fmaxf(mx1, fmaxf(s[nt][2], s[nt][3]));
        }
        mx0 = fmaxf(mx0, __shfl_xor_sync(0xffffffffu, mx0, 1));
        mx0 = fmaxf(mx0, __shfl_xor_sync(0xffffffffu, mx0, 2));
        mx1 = fmaxf(mx1, __shfl_xor_sync(0xffffffffu, mx1, 1));
        mx1 = fmaxf(mx1, __shfl_xor_sync(0xffffffffu, mx1, 2));
        float nm0 = fmaxf(m0, mx0), nm1 = fmaxf(m1, mx1);
        float cr0 = __expf(m0 - nm0), cr1 = __expf(m1 - nm1);
        l0 *= cr0; l1 *= cr1;
#pragma unroll
        for (int nt = 0; nt < 8; ++nt) {
            o[nt][0] *= cr0; o[nt][1] *= cr0;
            o[nt][2] *= cr1; o[nt][3] *= cr1;
        }
        float s0 = 0.f, s1 = 0.f;
#pragma unroll
        for (int nt = 0; nt < 16; ++nt) {
            float p00 = __expf(s[nt][0] - nm0);
            float p01 = __expf(s[nt][1] - nm0);
            float p10 = __expf(s[nt][2] - nm1);
            float p11 = __expf(s[nt][3] - nm1);
            s0 += p00 + p01; s1 += p10 + p11;
            *(__half2*)&Ps[(mb + g) * 128 + ((nt ^ g) * 8) + 2 * t] =
                __floats2half2_rn(p00, p01);
            *(__half2*)&Ps[(mb + g + 8) * 128 + ((nt ^ g) * 8) + 2 * t] =
                __floats2half2_rn(p10, p11);
        }
        s0 += __shfl_xor_sync(0xffffffffu, s0, 1);
        s0 += __shfl_xor_sync(0xffffffffu, s0, 2);
        s1 += __shfl_xor_sync(0xffffffffu, s1, 1);
        s1 += __shfl_xor_sync(0xffffffffu, s1, 2);
        l0 += s0; l1 += s1;
        m0 = nm0; m1 = nm1;
        __syncwarp();

        // O += P V
#pragma unroll
        for (int kb = 0; kb < 8; ++kb) {
            uint32_t pa0, pa1, pa2, pa3;
            {
                int row = mb + aRow;
                int seg = (2 * kb + hsel) ^ j;
                ldsm_x4(pa0, pa1, pa2, pa3, sb + (uint32_t)(row * 128 + seg * 8) * 2);
            }
            uint32_t vf[8][2];
#pragma unroll
            for (int p = 0; p < 4; ++p) {
                int n = p * 16 + bRow;
                int seg = (2 * kb + rsel) ^ j;
                ldsm_x4(vf[2 * p][0], vf[2 * p][1], vf[2 * p + 1][0], vf[2 * p + 1][1],
                        vsb + (uint32_t)(n * 128 + seg * 8) * 2);
            }
#pragma unroll
            for (int nt = 0; nt < 8; ++nt)
                mma_f16(o[nt][0], o[nt][1], o[nt][2], o[nt][3],
                        pa0, pa1, pa2, pa3, vf[nt][0], vf[nt][1]);
        }
    }

    const int b = bh >> 4, h = bh & 15;
    const float inv0 = 1.f / l0, inv1 = 1.f / l1;
    __half* O0 = g_ah + ((size_t)(b * TSEQ) + row0) * CEMB + h * HSIZE;
    __half* O1 = g_ah + ((size_t)(b * TSEQ) + row1) * CEMB + h * HSIZE;
#pragma unroll
    for (int nt = 0; nt < 8; ++nt) {
        int d = nt * 8 + 2 * t;
        *(__half2*)(O0 + d) = __floats2half2_rn(o[nt][0] * inv0, o[nt][1] * inv0);
        *(__half2*)(O1 + d) = __floats2half2_rn(o[nt][2] * inv1, o[nt][3] * inv1);
    }
}

// ---------------------------------------------------------------------------
extern "C" void kernel_launch(void* const* d_in, const int* in_sizes, int n_in,
                              void* d_out, int out_size)
{
    const float* x      = (const float*)d_in[0];
    const float* w_qkv  = (const float*)d_in[1];
    const float* w_proj = (const float*)d_in[2];
    const float* b_proj = (const float*)d_in[3];
    float* out = (float*)d_out;

    __half *xh = nullptr, *ah = nullptr, *wtq = nullptr, *wtp = nullptr;
    cudaGetSymbolAddress((void**)&xh,  g_xh);
    cudaGetSymbolAddress((void**)&ah,  g_ah);
    cudaGetSymbolAddress((void**)&wtq, g_wtq);
    cudaGetSymbolAddress((void**)&wtp, g_wtp);

    const int ATTN_SMEM = (AQP_H + 2 * KV_H) * 2;       // 81920
    const int GEMM_SMEM = GSTAGES * GST_H * 2;          // 98304
    cudaFuncSetAttribute(attn_h, cudaFuncAttributeMaxDynamicSharedMemorySize, ATTN_SMEM);
    cudaFuncSetAttribute(gemm_h, cudaFuncAttributeMaxDynamicSharedMemorySize, GEMM_SMEM);

    // 0) convert x, transpose weights (K-major, half)
    cvt_x<<<MROWS * CEMB / (256 * 8), 256>>>(x, xh);
    transpose_h<<<dim3(3 * CEMB / 32, CEMB / 32), dim3(32, 8)>>>(w_qkv, wtq, CEMB, 3 * CEMB);
    transpose_h<<<dim3(CEMB / 32, CEMB / 32), dim3(32, 8)>>>(w_proj, wtp, CEMB, CEMB);

    // 1) QKV GEMM (fp16 mma + ldmatrix, cp.async, 2 CTA/SM) + head-major scatter
    gemm_h<<<dim3(3 * CEMB / 128, MROWS / 128), 256, GEMM_SMEM>>>(
        xh, wtq, nullptr, nullptr, MROWS, 3 * CEMB, CEMB, 0);

    // 2) Causal flash attention (fp16 mma + ldmatrix, 128-thread CTAs)
    attn_h<<<dim3(TSEQ / 64, BATCH * NHEAD), 128, ATTN_SMEM>>>();

    // 3) Output projection + bias (fp16 mma + ldmatrix, fp32 out)
    gemm_h<<<dim3(CEMB / 128, MROWS / 128), 256, GEMM_SMEM>>>(
        ah, wtp, b_proj, out, MROWS, CEMB, CEMB, 1);
}

// round 15
// speedup vs baseline: 1.1323x; 1.0045x over previous
#include <cuda_runtime.h>
#include <cuda_fp16.h>
#include <math.h>
#include <stdint.h>

// Problem constants
#define BATCH   4
#define TSEQ    2048
#define NHEAD   16
#define HSIZE   64
#define CEMB    1024
#define MROWS   (BATCH*TSEQ)   // 8192

// Scratch (device globals; fp16 operands, fp32 accum everywhere)
__device__ __half g_xh [(size_t)MROWS * CEMB];
__device__ __half g_qh [(size_t)BATCH * NHEAD * TSEQ * HSIZE]; // [B,H,T,D], q pre-scaled
__device__ __half g_kh [(size_t)BATCH * NHEAD * TSEQ * HSIZE]; // [B,H,T,D]
__device__ __half g_vh [(size_t)BATCH * NHEAD * TSEQ * HSIZE]; // [B,H,T,D] (same as K!)
__device__ __half g_ah [(size_t)MROWS * CEMB];
__device__ __half g_wtq[(size_t)3 * CEMB * CEMB];              // [3C][C] K-major
__device__ __half g_wtp[(size_t)CEMB * CEMB];                  // [C][C]  K-major

// ---------------------------------------------------------------------------
// helpers
// ---------------------------------------------------------------------------
__device__ __forceinline__ void mma_f16(float& c0, float& c1, float& c2, float& c3,
                                        uint32_t a0, uint32_t a1, uint32_t a2, uint32_t a3,
                                        uint32_t b0, uint32_t b1) {
    asm volatile("mma.sync.aligned.m16n8k16.row.col.f32.f16.f16.f32 "
                 "{%0,%1,%2,%3}, {%4,%5,%6,%7}, {%8,%9}, {%0,%1,%2,%3};"
                 : "+f"(c0), "+f"(c1), "+f"(c2), "+f"(c3)
                 : "r"(a0), "r"(a1), "r"(a2), "r"(a3), "r"(b0), "r"(b1));
}
__device__ __forceinline__ void ldsm_x4(uint32_t& r0, uint32_t& r1, uint32_t& r2,
                                        uint32_t& r3, uint32_t addr) {
    asm volatile("ldmatrix.sync.aligned.m8n8.x4.shared.b16 {%0,%1,%2,%3}, [%4];"
                 : "=r"(r0), "=r"(r1), "=r"(r2), "=r"(r3) : "r"(addr));
}
__device__ __forceinline__ void ldsm_x4_t(uint32_t& r0, uint32_t& r1, uint32_t& r2,
                                          uint32_t& r3, uint32_t addr) {
    asm volatile("ldmatrix.sync.aligned.m8n8.x4.trans.shared.b16 {%0,%1,%2,%3}, [%4];"
                 : "=r"(r0), "=r"(r1), "=r"(r2), "=r"(r3) : "r"(addr));
}
__device__ __forceinline__ uint32_t h2u(__half2 h) { return *(uint32_t*)&h; }
__device__ __forceinline__ uint32_t smem_u32(const void* p) {
    uint32_t a;
    asm("{ .reg .u64 t; cvta.to.shared.u64 t, %1; cvt.u32.u64 %0, t; }" : "=r"(a) : "l"(p));
    return a;
}
#define CP_ASYNC16(dst, src) \
    asm volatile("cp.async.cg.shared.global [%0], [%1], 16;" :: "r"(dst), "l"(src))
#define CP_COMMIT()  asm volatile("cp.async.commit_group;" ::)
#define CP_WAIT(n)   asm volatile("cp.async.wait_group %0;" :: "n"(n))

// ---------------------------------------------------------------------------
// x -> half
// ---------------------------------------------------------------------------
__global__ __launch_bounds__(256) void cvt_x(const float* __restrict__ in,
                                             __half* __restrict__ out)
{
    size_t i = ((size_t)blockIdx.x * 256 + threadIdx.x) * 8;
    float4 v0 = *(const float4*)(in + i);
    float4 v1 = *(const float4*)(in + i + 4);
    uint4 u = {h2u(__floats2half2_rn(v0.x, v0.y)), h2u(__floats2half2_rn(v0.z, v0.w)),
               h2u(__floats2half2_rn(v1.x, v1.y)), h2u(__floats2half2_rn(v1.z, v1.w))};
    *(uint4*)(out + i) = u;
}

// ---------------------------------------------------------------------------
// Weight transpose fp32 [R][C] -> half [C][R]
// ---------------------------------------------------------------------------
__global__ __launch_bounds__(256) void transpose_h(const float* __restrict__ in,
                                                   __half* __restrict__ out, int R, int C)
{
    __shared__ float t[32][33];
    int bx = blockIdx.x * 32, by = blockIdx.y * 32;
#pragma unroll
    for (int i = 0; i < 32; i += 8)
        t[threadIdx.y + i][threadIdx.x] = in[(size_t)(by + threadIdx.y + i) * C + bx + threadIdx.x];
    __syncthreads();
#pragma unroll
    for (int i = 0; i < 32; i += 8)
        out[(size_t)(bx + threadIdx.y + i) * R + by + threadIdx.x] =
            __float2half_rn(t[threadIdx.x][threadIdx.y + i]);
}

// ---------------------------------------------------------------------------
// fp16 GEMM: 128x128 tile, cp.async 3-stage, 2 CTAs/SM, ldmatrix fragments.
// mode 0: Q/K/V all scatter as [B,H,T,D] with coalesced half2 stores.
// ---------------------------------------------------------------------------
#define GA_H   (128 * 64)
#define GB_H   (128 * 64)
#define GST_H  (GA_H + GB_H)      // 32KB per stage
#define GSTAGES 3
__global__ __launch_bounds__(256, 2) void gemm_h(
    const __half* __restrict__ A, const __half* __restrict__ Bt,
    const float* __restrict__ bias, float* __restrict__ C,
    int M, int N, int K, int mode)
{
    extern __shared__ __align__(16) __half hsm[];
    const uint32_t sb = smem_u32(hsm);

    const int tid  = threadIdx.x;
    const int wid  = tid >> 5;
    const int lane = tid & 31;
    const int g    = lane >> 2;
    const int t    = lane & 3;
    const int wm   = wid & 3;
    const int wn   = wid >> 2;
    const int m0 = blockIdx.y * 128;
    const int n0 = blockIdx.x * 128;

    const int lrA = tid >> 3;
    const int lsA = tid & 7;

    // ldmatrix per-thread selectors
    const int j    = lane & 7;
    const int hsel = lane >> 4;
    const int rsel = (lane >> 3) & 1;
    const int aRow = rsel * 8 + j;
    const int bRow = hsel * 8 + j;

    float c[2][8][4];
#pragma unroll
    for (int mt = 0; mt < 2; ++mt)
#pragma unroll
        for (int nt = 0; nt < 8; ++nt)
#pragma unroll
            for (int jj = 0; jj < 4; ++jj) c[mt][nt][jj] = 0.f;

    auto issue = [&](int s) {
        const int base = (s % GSTAGES) * GST_H;
        const int koff = (s << 6) + lsA * 8;
#pragma unroll
        for (int i = 0; i < 4; ++i) {
            int r = lrA + i * 32;
            uint32_t dst = sb + (uint32_t)(base + r * 64 + ((lsA ^ (r & 7)) * 8)) * 2;
            CP_ASYNC16(dst, A + (size_t)(m0 + r) * K + koff);
        }
#pragma unroll
        for (int i = 0; i < 4; ++i) {
            int r = lrA + i * 32;
            uint32_t dst = sb + (uint32_t)(base + GA_H + r * 64 + ((lsA ^ (r & 7)) * 8)) * 2;
            CP_ASYNC16(dst, Bt + (size_t)(n0 + r) * K + koff);
        }
        CP_COMMIT();
    };

    const int KS = K >> 6;
    issue(0);
    issue(1);

#pragma unroll 1
    for (int s = 0; s < KS; ++s) {
        if (s + 1 < KS) { CP_WAIT(1); } else { CP_WAIT(0); }
        __syncthreads();
        if (s + 2 < KS) issue(s + 2);

        const uint32_t stA = sb + (uint32_t)((s % GSTAGES) * GST_H) * 2;
        const uint32_t stB = stA + GA_H * 2;

#pragma unroll
        for (int kt = 0; kt < 4; ++kt) {
            uint32_t bf[8][2];
#pragma unroll
            for (int p = 0; p < 4; ++p) {
                int n = wn * 64 + p * 16 + bRow;
                int seg = (2 * kt + rsel) ^ j;
                ldsm_x4(bf[2 * p][0], bf[2 * p][1], bf[2 * p + 1][0], bf[2 * p + 1][1],
                        stB + (uint32_t)(n * 64 + seg * 8) * 2);
            }
#pragma unroll
            for (int mt = 0; mt < 2; ++mt) {
                int row = wm * 32 + mt * 16 + aRow;
                int seg = (2 * kt + hsel) ^ j;
                uint32_t a0, a1, a2, a3;
                ldsm_x4(a0, a1, a2, a3, stA + (uint32_t)(row * 64 + seg * 8) * 2);
#pragma unroll
                for (int nt = 0; nt < 8; ++nt)
                    mma_f16(c[mt][nt][0], c[mt][nt][1], c[mt][nt][2], c[mt][nt][3],
                            a0, a1, a2, a3, bf[nt][0], bf[nt][1]);
            }
        }
    }

    const int nbase = n0 + wn * 64;
    if (mode == 0) {
        const int which = nbase >> 10;
        const int h = (nbase & 1023) >> 6;
        const float sc = (which == 0) ? 0.125f : 1.0f;
        __half* base = (which == 0) ? g_qh : ((which == 1) ? g_kh : g_vh);
#pragma unroll
        for (int mt = 0; mt < 2; ++mt) {
            int r0 = m0 + wm * 32 + mt * 16 + g;
            int bb0 = r0 >> 11, tt0 = r0 & (TSEQ - 1);
            int r1 = r0 + 8;
            int bb1 = r1 >> 11, tt1 = r1 & (TSEQ - 1);
            __half* d0 = base + (((size_t)(bb0 * NHEAD + h) * TSEQ) + tt0) * HSIZE;
            __half* d1 = base + (((size_t)(bb1 * NHEAD + h) * TSEQ) + tt1) * HSIZE;
#pragma unroll
            for (int nt = 0; nt < 8; ++nt) {
                int d = nt * 8 + 2 * t;
                *(__half2*)(d0 + d) = __floats2half2_rn(c[mt][nt][0] * sc, c[mt][nt][1] * sc);
                *(__half2*)(d1 + d) = __floats2half2_rn(c[mt][nt][2] * sc, c[mt][nt][3] * sc);
            }
        }
    } else {
#pragma unroll
        for (int mt = 0; mt < 2; ++mt) {
            int r0 = m0 + wm * 32 + mt * 16 + g;
#pragma unroll
            for (int nt = 0; nt < 8; ++nt) {
                int n = nbase + nt * 8 + 2 * t;
                float2 bv = *(const float2*)(bias + n);
                float2 v0 = {c[mt][nt][0] + bv.x, c[mt][nt][1] + bv.y};
                float2 v1 = {c[mt][nt][2] + bv.x, c[mt][nt][3] + bv.y};
                *(float2*)(C + (size_t)r0 * N + n) = v0;
                *(float2*)(C + (size_t)(r0 + 8) * N + n) = v1;
            }
        }
    }
}

// ---------------------------------------------------------------------------
// fp16 causal flash attention: 128-thread CTAs (4 warps, 64 queries),
// cp.async double-buffered 128-key KV tiles, ldmatrix fragments.
// V stored [B,H,T,D] (same as K); PV B-fragments via ldmatrix.trans.
// Smem (halfs): QP 64x128, 2 x {K 128x64, V 128x64}. 80KB/CTA.
// ---------------------------------------------------------------------------
#define AQP_H (64 * 128)
#define AK_H  (128 * 64)
#define KV_H  (2 * AK_H)   // 16384 halfs per buffer
__global__ __launch_bounds__(128) void attn_h()
{
    extern __shared__ __align__(16) __half asm_[];
    __half* Qs = asm_;
    __half* Ps = Qs;
    const uint32_t sb = smem_u32(asm_);

    const int tid  = threadIdx.x;
    const int wid  = tid >> 5;          // 0..3
    const int lane = tid & 31;
    const int g    = lane >> 2;
    const int t    = lane & 3;
    const int mb   = wid * 16;
    const int bh   = blockIdx.y;
    const int qi   = gridDim.x - 1 - blockIdx.x;   // heavy CTAs first
    const int q0   = qi * 64;
    const int jmax = (q0 + 64 + 127) >> 7;

    // ldmatrix selectors
    const int j    = lane & 7;
    const int hsel = lane >> 4;
    const int rsel = (lane >> 3) & 1;
    const int aRow = rsel * 8 + j;
    const int bRow = hsel * 8 + j;
    const int vRow = rsel * 8 + j;      // trans-V row within 16-key block

    const __half* Kg = g_kh + (size_t)bh * TSEQ * HSIZE;
    const __half* Vg = g_vh + (size_t)bh * TSEQ * HSIZE;

    auto issueKV = [&](int jt) {
        const int base = AQP_H + (jt & 1) * KV_H;
#pragma unroll
        for (int i = 0; i < 8; ++i) {
            int f = tid + i * 128;
            int kr = f >> 3, ks = f & 7;
            uint32_t off = (uint32_t)(kr * 64 + ((ks ^ (kr & 7)) * 8)) * 2;
            CP_ASYNC16(sb + (uint32_t)base * 2 + off,
                       Kg + (size_t)(jt * 128 + kr) * HSIZE + ks * 8);
            CP_ASYNC16(sb + (uint32_t)(base + AK_H) * 2 + off,
                       Vg + (size_t)(jt * 128 + kr) * HSIZE + ks * 8);
        }
        CP_COMMIT();
    };

    issueKV(0);

    // stage Q tile [64][64] halfs
    const __half* Qg = g_qh + ((size_t)bh * TSEQ + q0) * HSIZE;
#pragma unroll
    for (int i = 0; i < 4; ++i) {
        int f = tid + i * 128;
        int r = f >> 3, s = f & 7;
        *(uint4*)&Qs[r * 64 + ((s ^ (r & 7)) * 8)] =
            *(const uint4*)(Qg + (size_t)r * HSIZE + s * 8);
    }
    __syncthreads();

    uint32_t qa[4][4];
#pragma unroll
    for (int kb = 0; kb < 4; ++kb) {
        int row = mb + aRow;
        int seg = (2 * kb + hsel) ^ j;
        ldsm_x4(qa[kb][0], qa[kb][1], qa[kb][2], qa[kb][3],
                sb + (uint32_t)(row * 64 + seg * 8) * 2);
    }

    float o[8][4];
#pragma unroll
    for (int nt = 0; nt < 8; ++nt)
#pragma unroll
        for (int jj = 0; jj < 4; ++jj) o[nt][jj] = 0.f;
    float m0 = -INFINITY, m1 = -INFINITY, l0 = 0.f, l1 = 0.f;

    const int row0 = q0 + mb + g;
    const int row1 = row0 + 8;

    for (int jt = 0; jt < jmax; ++jt) {
        CP_WAIT(0);
        __syncthreads();
        if (jt + 1 < jmax) issueKV(jt + 1);

        const uint32_t ksb = sb + (uint32_t)(AQP_H + (jt & 1) * KV_H) * 2;
        const uint32_t vsb = ksb + AK_H * 2;

        // S = Q K^T : 16 rows x 128 keys per warp
        float s[16][4];
#pragma unroll
        for (int nt = 0; nt < 16; ++nt)
#pragma unroll
            for (int jj = 0; jj < 4; ++jj) s[nt][jj] = 0.f;
#pragma unroll
        for (int kb = 0; kb < 4; ++kb) {
            uint32_t kf[16][2];
#pragma unroll
            for (int p = 0; p < 8; ++p) {
                int n = p * 16 + bRow;
                int seg = (2 * kb + rsel) ^ j;
                ldsm_x4(kf[2 * p][0], kf[2 * p][1], kf[2 * p + 1][0], kf[2 * p + 1][1],
                        ksb + (uint32_t)(n * 64 + seg * 8) * 2);
            }
#pragma unroll
            for (int nt = 0; nt < 16; ++nt)
                mma_f16(s[nt][0], s[nt][1], s[nt][2], s[nt][3],
                        qa[kb][0], qa[kb][1], qa[kb][2], qa[kb][3],
                        kf[nt][0], kf[nt][1]);
        }

        // causal mask (last tile only)
        if (jt == jmax - 1) {
#pragma unroll
            for (int nt = 0; nt < 16; ++nt) {
                int col = jt * 128 + nt * 8 + 2 * t;
                if (col > row0)     s[nt][0] = -INFINITY;
                if (col + 1 > row0) s[nt][1] = -INFINITY;
                if (col > row1)     s[nt][2] = -INFINITY;
                if (col + 1 > row1) s[nt][3] = -INFINITY;
            }
        }

        // online softmax (fp32)
        float mx0 = -INFINITY, mx1 = -INFINITY;
#pragma unroll
        for (int nt = 0; nt < 16; ++nt) {
            mx0 = fmaxf(mx0, fmaxf(s[nt][0], s[nt][1]));
            mx1 = fmaxf(mx1, fmaxf(s[nt][2], s[nt][3]));
        }
        mx0 = fmaxf(mx0, __shfl_xor_sync(0xffffffffu, mx0, 1));
        mx0 = fmaxf(mx0, __shfl_xor_sync(0xffffffffu, mx0, 2));
        mx1 = fmaxf(mx1, __shfl_xor_sync(0xffffffffu, mx1, 1));
        mx1 = fmaxf(mx1, __shfl_xor_sync(0xffffffffu, mx1, 2));
        float nm0 = fmaxf(m0, mx0), nm1 = fmaxf(m1, mx1);
        float cr0 = __expf(m0 - nm0), cr1 = __expf(m1 - nm1);
        l0 *= cr0; l1 *= cr1;
#pragma unroll
        for (int nt = 0; nt < 8; ++nt) {
            o[nt][0] *= cr0; o[nt][1] *= cr0;
            o[nt][2] *= cr1; o[nt][3] *= cr1;
        }
        float s0 = 0.f, s1 = 0.f;
#pragma unroll
        for (int nt = 0; nt < 16; ++nt) {
            float p00 = __expf(s[nt][0] - nm0);
            float p01 = __expf(s[nt][1] - nm0);
            float p10 = __expf(s[nt][2] - nm1);
            float p11 = __expf(s[nt][3] - nm1);
            s0 += p00 + p01; s1 += p10 + p11;
            *(__half2*)&Ps[(mb + g) * 128 + ((nt ^ g) * 8) + 2 * t] =
                __floats2half2_rn(p00, p01);
            *(__half2*)&Ps[(mb + g + 8) * 128 + ((nt ^ g) * 8) + 2 * t] =
                __floats2half2_rn(p10, p11);
        }
        s0 += __shfl_xor_sync(0xffffffffu, s0, 1);
        s0 += __shfl_xor_sync(0xffffffffu, s0, 2);
        s1 += __shfl_xor_sync(0xffffffffu, s1, 1);
        s1 += __shfl_xor_sync(0xffffffffu, s1, 2);
        l0 += s0; l1 += s1;
        m0 = nm0; m1 = nm1;
        __syncwarp();

        // O += P V : V B-fragments via ldmatrix.trans on [key][d] tile
#pragma unroll
        for (int kb = 0; kb < 8; ++kb) {
            uint32_t pa0, pa1, pa2, pa3;
            {
                int row = mb + aRow;
                int seg = (2 * kb + hsel) ^ j;
                ldsm_x4(pa0, pa1, pa2, pa3, sb + (uint32_t)(row * 128 + seg * 8) * 2);
            }
            uint32_t vf[8][2];
            const int vrow = kb * 16 + vRow;       // key row
#pragma unroll
            for (int p = 0; p < 4; ++p) {
                int seg = (2 * p + hsel) ^ (vrow & 7);
                ldsm_x4_t(vf[2 * p][0], vf[2 * p][1], vf[2 * p + 1][0], vf[2 * p + 1][1],
                          vsb + (uint32_t)(vrow * 64 + seg * 8) * 2);
            }
#pragma unroll
            for (int nt = 0; nt < 8; ++nt)
                mma_f16(o[nt][0], o[nt][1], o[nt][2], o[nt][3],
                        pa0, pa1, pa2, pa3, vf[nt][0], vf[nt][1]);
        }
    }

    const int b = bh >> 4, h = bh & 15;
    const float inv0 = 1.f / l0, inv1 = 1.f / l1;
    __half* O0 = g_ah + ((size_t)(b * TSEQ) + row0) * CEMB + h * HSIZE;
    __half* O1 = g_ah + ((size_t)(b * TSEQ) + row1) * CEMB + h * HSIZE;
#pragma unroll
    for (int nt = 0; nt < 8; ++nt) {
        int d = nt * 8 + 2 * t;
        *(__half2*)(O0 + d) = __floats2half2_rn(o[nt][0] * inv0, o[nt][1] * inv0);
        *(__half2*)(O1 + d) = __floats2half2_rn(o[nt][2] * inv1, o[nt][3] * inv1);
    }
}

// ---------------------------------------------------------------------------
extern "C" void kernel_launch(void* const* d_in, const int* in_sizes, int n_in,
                              void* d_out, int out_size)
{
    const float* x      = (const float*)d_in[0];
    const float* w_qkv  = (const float*)d_in[1];
    const float* w_proj = (const float*)d_in[2];
    const float* b_proj = (const float*)d_in[3];
    float* out = (float*)d_out;

    __half *xh = nullptr, *ah = nullptr, *wtq = nullptr, *wtp = nullptr;
    cudaGetSymbolAddress((void**)&xh,  g_xh);
    cudaGetSymbolAddress((void**)&ah,  g_ah);
    cudaGetSymbolAddress((void**)&wtq, g_wtq);
    cudaGetSymbolAddress((void**)&wtp, g_wtp);

    const int ATTN_SMEM = (AQP_H + 2 * KV_H) * 2;       // 81920
    const int GEMM_SMEM = GSTAGES * GST_H * 2;          // 98304
    cudaFuncSetAttribute(attn_h, cudaFuncAttributeMaxDynamicSharedMemorySize, ATTN_SMEM);
    cudaFuncSetAttribute(gemm_h, cudaFuncAttributeMaxDynamicSharedMemorySize, GEMM_SMEM);

    // 0) convert x, transpose weights (K-major, half)
    cvt_x<<<MROWS * CEMB / (256 * 8), 256>>>(x, xh);
    transpose_h<<<dim3(3 * CEMB / 32, CEMB / 32), dim3(32, 8)>>>(w_qkv, wtq, CEMB, 3 * CEMB);
    transpose_h<<<dim3(CEMB / 32, CEMB / 32), dim3(32, 8)>>>(w_proj, wtp, CEMB, CEMB);

    // 1) QKV GEMM (fp16 mma + ldmatrix, cp.async, 2 CTA/SM); V now coalesced
    gemm_h<<<dim3(3 * CEMB / 128, MROWS / 128), 256, GEMM_SMEM>>>(
        xh, wtq, nullptr, nullptr, MROWS, 3 * CEMB, CEMB, 0);

    // 2) Causal flash attention (fp16 mma + ldmatrix/.trans, 128-thread CTAs)
    attn_h<<<dim3(TSEQ / 64, BATCH * NHEAD), 128, ATTN_SMEM>>>();

    // 3) Output projection + bias
    gemm_h<<<dim3(CEMB / 128, MROWS / 128), 256, GEMM_SMEM>>>(
        ah, wtp, b_proj, out, MROWS, CEMB, CEMB, 1);
}

// round 16
// speedup vs baseline: 1.2293x; 1.0857x over previous
#include <cuda_runtime.h>
#include <cuda_fp16.h>
#include <math.h>
#include <stdint.h>

// Problem constants
#define BATCH   4
#define TSEQ    2048
#define NHEAD   16
#define HSIZE   64
#define CEMB    1024
#define MROWS   (BATCH*TSEQ)   // 8192

// Scratch (device globals; fp16 operands, fp32 accum everywhere)
__device__ __half g_xh [(size_t)MROWS * CEMB];
__device__ __half g_qh [(size_t)BATCH * NHEAD * TSEQ * HSIZE]; // [B,H,T,D], q pre-scaled
__device__ __half g_kh [(size_t)BATCH * NHEAD * TSEQ * HSIZE]; // [B,H,T,D]
__device__ __half g_vh [(size_t)BATCH * NHEAD * TSEQ * HSIZE]; // [B,H,T,D]
__device__ __half g_ah [(size_t)MROWS * CEMB];
__device__ __half g_wtq[(size_t)3 * CEMB * CEMB];              // [3C][C] K-major
__device__ __half g_wtp[(size_t)CEMB * CEMB];                  // [C][C]  K-major

// ---------------------------------------------------------------------------
// helpers
// ---------------------------------------------------------------------------
__device__ __forceinline__ void mma_f16(float& c0, float& c1, float& c2, float& c3,
                                        uint32_t a0, uint32_t a1, uint32_t a2, uint32_t a3,
                                        uint32_t b0, uint32_t b1) {
    asm volatile("mma.sync.aligned.m16n8k16.row.col.f32.f16.f16.f32 "
                 "{%0,%1,%2,%3}, {%4,%5,%6,%7}, {%8,%9}, {%0,%1,%2,%3};"
                 : "+f"(c0), "+f"(c1), "+f"(c2), "+f"(c3)
                 : "r"(a0), "r"(a1), "r"(a2), "r"(a3), "r"(b0), "r"(b1));
}
__device__ __forceinline__ void ldsm_x4(uint32_t& r0, uint32_t& r1, uint32_t& r2,
                                        uint32_t& r3, uint32_t addr) {
    asm volatile("ldmatrix.sync.aligned.m8n8.x4.shared.b16 {%0,%1,%2,%3}, [%4];"
                 : "=r"(r0), "=r"(r1), "=r"(r2), "=r"(r3) : "r"(addr));
}
__device__ __forceinline__ void ldsm_x4_t(uint32_t& r0, uint32_t& r1, uint32_t& r2,
                                          uint32_t& r3, uint32_t addr) {
    asm volatile("ldmatrix.sync.aligned.m8n8.x4.trans.shared.b16 {%0,%1,%2,%3}, [%4];"
                 : "=r"(r0), "=r"(r1), "=r"(r2), "=r"(r3) : "r"(addr));
}
__device__ __forceinline__ uint32_t h2u(__half2 h) { return *(uint32_t*)&h; }
__device__ __forceinline__ uint32_t smem_u32(const void* p) {
    uint32_t a;
    asm("{ .reg .u64 t; cvta.to.shared.u64 t, %1; cvt.u32.u64 %0, t; }" : "=r"(a) : "l"(p));
    return a;
}
#define CP_ASYNC16(dst, src) \
    asm volatile("cp.async.cg.shared.global [%0], [%1], 16;" :: "r"(dst), "l"(src))
#define CP_COMMIT()  asm volatile("cp.async.commit_group;" ::)
#define CP_WAIT(n)   asm volatile("cp.async.wait_group %0;" :: "n"(n))

// ---------------------------------------------------------------------------
// x -> half
// ---------------------------------------------------------------------------
__global__ __launch_bounds__(256) void cvt_x(const float* __restrict__ in,
                                             __half* __restrict__ out)
{
    size_t i = ((size_t)blockIdx.x * 256 + threadIdx.x) * 8;
    float4 v0 = *(const float4*)(in + i);
    float4 v1 = *(const float4*)(in + i + 4);
    uint4 u = {h2u(__floats2half2_rn(v0.x, v0.y)), h2u(__floats2half2_rn(v0.z, v0.w)),
               h2u(__floats2half2_rn(v1.x, v1.y)), h2u(__floats2half2_rn(v1.z, v1.w))};
    *(uint4*)(out + i) = u;
}

// ---------------------------------------------------------------------------
// Weight transpose fp32 [R][C] -> half [C][R]
// ---------------------------------------------------------------------------
__global__ __launch_bounds__(256) void transpose_h(const float* __restrict__ in,
                                                   __half* __restrict__ out, int R, int C)
{
    __shared__ float t[32][33];
    int bx = blockIdx.x * 32, by = blockIdx.y * 32;
#pragma unroll
    for (int i = 0; i < 32; i += 8)
        t[threadIdx.y + i][threadIdx.x] = in[(size_t)(by + threadIdx.y + i) * C + bx + threadIdx.x];
    __syncthreads();
#pragma unroll
    for (int i = 0; i < 32; i += 8)
        out[(size_t)(bx + threadIdx.y + i) * R + by + threadIdx.x] =
            __float2half_rn(t[threadIdx.x][threadIdx.y + i]);
}

// ---------------------------------------------------------------------------
// fp16 GEMM: 128x128 tile, cp.async 3-stage, 2 CTAs/SM, ldmatrix fragments.
// (round-15 version, measured best)
// ---------------------------------------------------------------------------
#define GA_H   (128 * 64)
#define GB_H   (128 * 64)
#define GST_H  (GA_H + GB_H)      // 32KB per stage
#define GSTAGES 3
__global__ __launch_bounds__(256, 2) void gemm_h(
    const __half* __restrict__ A, const __half* __restrict__ Bt,
    const float* __restrict__ bias, float* __restrict__ C,
    int M, int N, int K, int mode)
{
    extern __shared__ __align__(16) __half hsm[];
    const uint32_t sb = smem_u32(hsm);

    const int tid  = threadIdx.x;
    const int wid  = tid >> 5;
    const int lane = tid & 31;
    const int g    = lane >> 2;
    const int t    = lane & 3;
    const int wm   = wid & 3;
    const int wn   = wid >> 2;
    const int m0 = blockIdx.y * 128;
    const int n0 = blockIdx.x * 128;

    const int lrA = tid >> 3;
    const int lsA = tid & 7;

    const int j    = lane & 7;
    const int hsel = lane >> 4;
    const int rsel = (lane >> 3) & 1;
    const int aRow = rsel * 8 + j;
    const int bRow = hsel * 8 + j;

    float c[2][8][4];
#pragma unroll
    for (int mt = 0; mt < 2; ++mt)
#pragma unroll
        for (int nt = 0; nt < 8; ++nt)
#pragma unroll
            for (int jj = 0; jj < 4; ++jj) c[mt][nt][jj] = 0.f;

    auto issue = [&](int s) {
        const int base = (s % GSTAGES) * GST_H;
        const int koff = (s << 6) + lsA * 8;
#pragma unroll
        for (int i = 0; i < 4; ++i) {
            int r = lrA + i * 32;
            uint32_t dst = sb + (uint32_t)(base + r * 64 + ((lsA ^ (r & 7)) * 8)) * 2;
            CP_ASYNC16(dst, A + (size_t)(m0 + r) * K + koff);
        }
#pragma unroll
        for (int i = 0; i < 4; ++i) {
            int r = lrA + i * 32;
            uint32_t dst = sb + (uint32_t)(base + GA_H + r * 64 + ((lsA ^ (r & 7)) * 8)) * 2;
            CP_ASYNC16(dst, Bt + (size_t)(n0 + r) * K + koff);
        }
        CP_COMMIT();
    };

    const int KS = K >> 6;
    issue(0);
    issue(1);

#pragma unroll 1
    for (int s = 0; s < KS; ++s) {
        if (s + 1 < KS) { CP_WAIT(1); } else { CP_WAIT(0); }
        __syncthreads();
        if (s + 2 < KS) issue(s + 2);

        const uint32_t stA = sb + (uint32_t)((s % GSTAGES) * GST_H) * 2;
        const uint32_t stB = stA + GA_H * 2;

#pragma unroll
        for (int kt = 0; kt < 4; ++kt) {
            uint32_t bf[8][2];
#pragma unroll
            for (int p = 0; p < 4; ++p) {
                int n = wn * 64 + p * 16 + bRow;
                int seg = (2 * kt + rsel) ^ j;
                ldsm_x4(bf[2 * p][0], bf[2 * p][1], bf[2 * p + 1][0], bf[2 * p + 1][1],
                        stB + (uint32_t)(n * 64 + seg * 8) * 2);
            }
#pragma unroll
            for (int mt = 0; mt < 2; ++mt) {
                int row = wm * 32 + mt * 16 + aRow;
                int seg = (2 * kt + hsel) ^ j;
                uint32_t a0, a1, a2, a3;
                ldsm_x4(a0, a1, a2, a3, stA + (uint32_t)(row * 64 + seg * 8) * 2);
#pragma unroll
                for (int nt = 0; nt < 8; ++nt)
                    mma_f16(c[mt][nt][0], c[mt][nt][1], c[mt][nt][2], c[mt][nt][3],
                            a0, a1, a2, a3, bf[nt][0], bf[nt][1]);
            }
        }
    }

    const int nbase = n0 + wn * 64;
    if (mode == 0) {
        const int which = nbase >> 10;
        const int h = (nbase & 1023) >> 6;
        const float sc = (which == 0) ? 0.125f : 1.0f;
        __half* base = (which == 0) ? g_qh : ((which == 1) ? g_kh : g_vh);
#pragma unroll
        for (int mt = 0; mt < 2; ++mt) {
            int r0 = m0 + wm * 32 + mt * 16 + g;
            int bb0 = r0 >> 11, tt0 = r0 & (TSEQ - 1);
            int r1 = r0 + 8;
            int bb1 = r1 >> 11, tt1 = r1 & (TSEQ - 1);
            __half* d0 = base + (((size_t)(bb0 * NHEAD + h) * TSEQ) + tt0) * HSIZE;
            __half* d1 = base + (((size_t)(bb1 * NHEAD + h) * TSEQ) + tt1) * HSIZE;
#pragma unroll
            for (int nt = 0; nt < 8; ++nt) {
                int d = nt * 8 + 2 * t;
                *(__half2*)(d0 + d) = __floats2half2_rn(c[mt][nt][0] * sc, c[mt][nt][1] * sc);
                *(__half2*)(d1 + d) = __floats2half2_rn(c[mt][nt][2] * sc, c[mt][nt][3] * sc);
            }
        }
    } else {
#pragma unroll
        for (int mt = 0; mt < 2; ++mt) {
            int r0 = m0 + wm * 32 + mt * 16 + g;
#pragma unroll
            for (int nt = 0; nt < 8; ++nt) {
                int n = nbase + nt * 8 + 2 * t;
                float2 bv = *(const float2*)(bias + n);
                float2 v0 = {c[mt][nt][0] + bv.x, c[mt][nt][1] + bv.y};
                float2 v1 = {c[mt][nt][2] + bv.x, c[mt][nt][3] + bv.y};
                *(float2*)(C + (size_t)r0 * N + n) = v0;
                *(float2*)(C + (size_t)(r0 + 8) * N + n) = v1;
            }
        }
    }
}

// ---------------------------------------------------------------------------
// fp16 causal flash attention: 128-thread CTAs (4 warps, 64 queries),
// cp.async double-buffered 128-key KV tiles, ldmatrix fragments,
// REGISTER-DIRECT P: fp16 m16n8k16 C-fragment layout == A-fragment layout,
// so exp(S) is packed straight into PV A-operands (no smem round-trip).
// Smem (halfs): Q 64x64 (8KB) + 2 x {K 128x64, V 128x64} (64KB) = 72KB/CTA.
// ---------------------------------------------------------------------------
#define AQ_H  (64 * 64)
#define AK_H  (128 * 64)
#define KV_H  (2 * AK_H)   // 16384 halfs per buffer
__global__ __launch_bounds__(128) void attn_h()
{
    extern __shared__ __align__(16) __half asm_[];
    __half* Qs = asm_;
    const uint32_t sb = smem_u32(asm_);

    const int tid  = threadIdx.x;
    const int wid  = tid >> 5;          // 0..3
    const int lane = tid & 31;
    const int g    = lane >> 2;
    const int t    = lane & 3;
    const int mb   = wid * 16;
    const int bh   = blockIdx.y;
    const int qi   = gridDim.x - 1 - blockIdx.x;   // heavy CTAs first
    const int q0   = qi * 64;
    const int jmax = (q0 + 64 + 127) >> 7;

    const int j    = lane & 7;
    const int hsel = lane >> 4;
    const int rsel = (lane >> 3) & 1;
    const int aRow = rsel * 8 + j;
    const int bRow = hsel * 8 + j;
    const int vRow = rsel * 8 + j;

    const __half* Kg = g_kh + (size_t)bh * TSEQ * HSIZE;
    const __half* Vg = g_vh + (size_t)bh * TSEQ * HSIZE;

    auto issueKV = [&](int jt) {
        const int base = AQ_H + (jt & 1) * KV_H;
#pragma unroll
        for (int i = 0; i < 8; ++i) {
            int f = tid + i * 128;
            int kr = f >> 3, ks = f & 7;
            uint32_t off = (uint32_t)(kr * 64 + ((ks ^ (kr & 7)) * 8)) * 2;
            CP_ASYNC16(sb + (uint32_t)base * 2 + off,
                       Kg + (size_t)(jt * 128 + kr) * HSIZE + ks * 8);
            CP_ASYNC16(sb + (uint32_t)(base + AK_H) * 2 + off,
                       Vg + (size_t)(jt * 128 + kr) * HSIZE + ks * 8);
        }
        CP_COMMIT();
    };

    issueKV(0);

    // stage Q tile [64][64] halfs
    const __half* Qg = g_qh + ((size_t)bh * TSEQ + q0) * HSIZE;
#pragma unroll
    for (int i = 0; i < 4; ++i) {
        int f = tid + i * 128;
        int r = f >> 3, s = f & 7;
        *(uint4*)&Qs[r * 64 + ((s ^ (r & 7)) * 8)] =
            *(const uint4*)(Qg + (size_t)r * HSIZE + s * 8);
    }
    __syncthreads();

    uint32_t qa[4][4];
#pragma unroll
    for (int kb = 0; kb < 4; ++kb) {
        int row = mb + aRow;
        int seg = (2 * kb + hsel) ^ j;
        ldsm_x4(qa[kb][0], qa[kb][1], qa[kb][2], qa[kb][3],
                sb + (uint32_t)(row * 64 + seg * 8) * 2);
    }

    float o[8][4];
#pragma unroll
    for (int nt = 0; nt < 8; ++nt)
#pragma unroll
        for (int jj = 0; jj < 4; ++jj) o[nt][jj] = 0.f;
    float m0 = -INFINITY, m1 = -INFINITY, l0 = 0.f, l1 = 0.f;

    const int row0 = q0 + mb + g;
    const int row1 = row0 + 8;

    for (int jt = 0; jt < jmax; ++jt) {
        CP_WAIT(0);
        __syncthreads();
        if (jt + 1 < jmax) issueKV(jt + 1);

        const uint32_t ksb = sb + (uint32_t)(AQ_H + (jt & 1) * KV_H) * 2;
        const uint32_t vsb = ksb + AK_H * 2;

        // S = Q K^T : 16 rows x 128 keys per warp
        float s[16][4];
#pragma unroll
        for (int nt = 0; nt < 16; ++nt)
#pragma unroll
            for (int jj = 0; jj < 4; ++jj) s[nt][jj] = 0.f;
#pragma unroll
        for (int kb = 0; kb < 4; ++kb) {
            uint32_t kf[16][2];
#pragma unroll
            for (int p = 0; p < 8; ++p) {
                int n = p * 16 + bRow;
                int seg = (2 * kb + rsel) ^ j;
                ldsm_x4(kf[2 * p][0], kf[2 * p][1], kf[2 * p + 1][0], kf[2 * p + 1][1],
                        ksb + (uint32_t)(n * 64 + seg * 8) * 2);
            }
#pragma unroll
            for (int nt = 0; nt < 16; ++nt)
                mma_f16(s[nt][0], s[nt][1], s[nt][2], s[nt][3],
                        qa[kb][0], qa[kb][1], qa[kb][2], qa[kb][3],
                        kf[nt][0], kf[nt][1]);
        }

        // causal mask (last tile only)
        if (jt == jmax - 1) {
#pragma unroll
            for (int nt = 0; nt < 16; ++nt) {
                int col = jt * 128 + nt * 8 + 2 * t;
                if (col > row0)     s[nt][0] = -INFINITY;
                if (col + 1 > row0) s[nt][1] = -INFINITY;
                if (col > row1)     s[nt][2] = -INFINITY;
                if (col + 1 > row1) s[nt][3] = -INFINITY;
            }
        }

        // online softmax (fp32); pack P straight into A-fragments
        float mx0 = -INFINITY, mx1 = -INFINITY;
#pragma unroll
        for (int nt = 0; nt < 16; ++nt) {
            mx0 = fmaxf(mx0, fmaxf(s[nt][0], s[nt][1]));
            mx1 = fmaxf(mx1, fmaxf(s[nt][2], s[nt][3]));
        }
        mx0 = fmaxf(mx0, __shfl_xor_sync(0xffffffffu, mx0, 1));
        mx0 = fmaxf(mx0, __shfl_xor_sync(0xffffffffu, mx0, 2));
        mx1 = fmaxf(mx1, __shfl_xor_sync(0xffffffffu, mx1, 1));
        mx1 = fmaxf(mx1, __shfl_xor_sync(0xffffffffu, mx1, 2));
        float nm0 = fmaxf(m0, mx0), nm1 = fmaxf(m1, mx1);
        float cr0 = __expf(m0 - nm0), cr1 = __expf(m1 - nm1);
        l0 *= cr0; l1 *= cr1;
#pragma unroll
        for (int nt = 0; nt < 8; ++nt) {
            o[nt][0] *= cr0; o[nt][1] *= cr0;
            o[nt][2] *= cr1; o[nt][3] *= cr1;
        }
        uint32_t pf[8][4];   // A-fragments of P: [kb][a0..a3]
        float s0 = 0.f, s1 = 0.f;
#pragma unroll
        for (int nt = 0; nt < 16; ++nt) {
            float p00 = __expf(s[nt][0] - nm0);
            float p01 = __expf(s[nt][1] - nm0);
            float p10 = __expf(s[nt][2] - nm1);
            float p11 = __expf(s[nt][3] - nm1);
            s0 += p00 + p01; s1 += p10 + p11;
            const int kb = nt >> 1;
            if ((nt & 1) == 0) {
                pf[kb][0] = h2u(__floats2half2_rn(p00, p01));
                pf[kb][1] = h2u(__floats2half2_rn(p10, p11));
            } else {
                pf[kb][2] = h2u(__floats2half2_rn(p00, p01));
                pf[kb][3] = h2u(__floats2half2_rn(p10, p11));
            }
        }
        s0 += __shfl_xor_sync(0xffffffffu, s0, 1);
        s0 += __shfl_xor_sync(0xffffffffu, s0, 2);
        s1 += __shfl_xor_sync(0xffffffffu, s1, 1);
        s1 += __shfl_xor_sync(0xffffffffu, s1, 2);
        l0 += s0; l1 += s1;
        m0 = nm0; m1 = nm1;

        // O += P V : P from registers, V B-frags via ldmatrix.trans
#pragma unroll
        for (int kb = 0; kb < 8; ++kb) {
            uint32_t vf[8][2];
            const int vrow = kb * 16 + vRow;
#pragma unroll
            for (int p = 0; p < 4; ++p) {
                int seg = (2 * p + hsel) ^ (vrow & 7);
                ldsm_x4_t(vf[2 * p][0], vf[2 * p][1], vf[2 * p + 1][0], vf[2 * p + 1][1],
                          vsb + (uint32_t)(vrow * 64 + seg * 8) * 2);
            }
#pragma unroll
            for (int nt = 0; nt < 8; ++nt)
                mma_f16(o[nt][0], o[nt][1], o[nt][2], o[nt][3],
                        pf[kb][0], pf[kb][1], pf[kb][2], pf[kb][3],
                        vf[nt][0], vf[nt][1]);
        }
    }

    const int b = bh >> 4, h = bh & 15;
    const float inv0 = 1.f / l0, inv1 = 1.f / l1;
    __half* O0 = g_ah + ((size_t)(b * TSEQ) + row0) * CEMB + h * HSIZE;
    __half* O1 = g_ah + ((size_t)(b * TSEQ) + row1) * CEMB + h * HSIZE;
#pragma unroll
    for (int nt = 0; nt < 8; ++nt) {
        int d = nt * 8 + 2 * t;
        *(__half2*)(O0 + d) = __floats2half2_rn(o[nt][0] * inv0, o[nt][1] * inv0);
        *(__half2*)(O1 + d) = __floats2half2_rn(o[nt][2] * inv1, o[nt][3] * inv1);
    }
}

// ---------------------------------------------------------------------------
extern "C" void kernel_launch(void* const* d_in, const int* in_sizes, int n_in,
                              void* d_out, int out_size)
{
    const float* x      = (const float*)d_in[0];
    const float* w_qkv  = (const float*)d_in[1];
    const float* w_proj = (const float*)d_in[2];
    const float* b_proj = (const float*)d_in[3];
    float* out = (float*)d_out;

    __half *xh = nullptr, *ah = nullptr, *wtq = nullptr, *wtp = nullptr;
    cudaGetSymbolAddress((void**)&xh,  g_xh);
    cudaGetSymbolAddress((void**)&ah,  g_ah);
    cudaGetSymbolAddress((void**)&wtq, g_wtq);
    cudaGetSymbolAddress((void**)&wtp, g_wtp);

    const int ATTN_SMEM = (AQ_H + 2 * KV_H) * 2;        // 73728
    const int GEMM_SMEM = GSTAGES * GST_H * 2;          // 98304
    cudaFuncSetAttribute(attn_h, cudaFuncAttributeMaxDynamicSharedMemorySize, ATTN_SMEM);
    cudaFuncSetAttribute(gemm_h, cudaFuncAttributeMaxDynamicSharedMemorySize, GEMM_SMEM);

    // 0) convert x, transpose weights (K-major, half)
    cvt_x<<<MROWS * CEMB / (256 * 8), 256>>>(x, xh);
    transpose_h<<<dim3(3 * CEMB / 32, CEMB / 32), dim3(32, 8)>>>(w_qkv, wtq, CEMB, 3 * CEMB);
    transpose_h<<<dim3(CEMB / 32, CEMB / 32), dim3(32, 8)>>>(w_proj, wtp, CEMB, CEMB);

    // 1) QKV GEMM (fp16 mma + ldmatrix, cp.async, 2 CTA/SM)
    gemm_h<<<dim3(3 * CEMB / 128, MROWS / 128), 256, GEMM_SMEM>>>(
        xh, wtq, nullptr, nullptr, MROWS, 3 * CEMB, CEMB, 0);

    // 2) Causal flash attention (register-direct P, ldmatrix/.trans)
    attn_h<<<dim3(TSEQ / 64, BATCH * NHEAD), 128, ATTN_SMEM>>>();

    // 3) Output projection + bias
    gemm_h<<<dim3(CEMB / 128, MROWS / 128), 256, GEMM_SMEM>>>(
        ah, wtp, b_proj, out, MROWS, CEMB, CEMB, 1);
}